// round 1
// baseline (speedup 1.0000x reference)
#include <cuda_runtime.h>
#include <cuda_bf16.h>
#include <math.h>

// Problem constants
#define BATCH 4
#define SEQ   2048
#define EMB   1024
#define HEAD  64
#define NROWS (BATCH * SEQ)   // 8192

// ---------------- scratch (q, k, v projections) ----------------
__device__ float g_q[NROWS * HEAD];
__device__ float g_k[NROWS * HEAD];
__device__ float g_v[NROWS * HEAD];

// ================= Kernel 1: LayerNorm + QKV projection =================
// 16 rows per block, 256 threads. Thread tile: 4 rows x 3 cols (192 cols = q|k|v).
#define K1_ROWS 16
#define K1_KC   32
#define K1_WPAD 36  // padded row stride for weight chunk in smem
// smem: xn[16*1024] + wch[192*36]
#define K1_SMEM ((K1_ROWS * EMB + 192 * K1_WPAD) * sizeof(float))

__global__ void __launch_bounds__(256, 2)
ln_qkv_kernel(const float* __restrict__ x,
              const float* __restrict__ gamma,
              const float* __restrict__ beta,
              const float* __restrict__ Wq,
              const float* __restrict__ Wk,
              const float* __restrict__ Wv)
{
    extern __shared__ float sm1[];
    float* xn  = sm1;                      // [16][1024]
    float* wch = sm1 + K1_ROWS * EMB;      // [192][36]

    const int tid  = threadIdx.x;
    const int warp = tid >> 5;
    const int lane = tid & 31;
    const int rowBase = blockIdx.x * K1_ROWS;

    // ---------- LayerNorm: warp w handles rows 2w, 2w+1 ----------
    #pragma unroll
    for (int rr = 0; rr < 2; rr++) {
        const int r = warp * 2 + rr;
        const float4* xr = (const float4*)(x + (size_t)(rowBase + r) * EMB);
        float4 v[8];
        float sum = 0.f, sq = 0.f;
        #pragma unroll
        for (int t = 0; t < 8; t++) {
            v[t] = xr[lane + 32 * t];
            sum += v[t].x + v[t].y + v[t].z + v[t].w;
            sq  += v[t].x*v[t].x + v[t].y*v[t].y + v[t].z*v[t].z + v[t].w*v[t].w;
        }
        #pragma unroll
        for (int off = 16; off; off >>= 1) {
            sum += __shfl_xor_sync(0xffffffffu, sum, off);
            sq  += __shfl_xor_sync(0xffffffffu, sq,  off);
        }
        const float inv = 1.0f / (float)EMB;
        const float mu = sum * inv;
        const float var = sq * inv - mu * mu;
        const float rstd = rsqrtf(var + 1e-5f);
        float4* xnr = (float4*)(xn + r * EMB);
        const float4* g4 = (const float4*)gamma;
        const float4* b4 = (const float4*)beta;
        #pragma unroll
        for (int t = 0; t < 8; t++) {
            const int i4 = lane + 32 * t;
            float4 gg = g4[i4], bb = b4[i4], xv = v[t], o;
            o.x = (xv.x - mu) * rstd * gg.x + bb.x;
            o.y = (xv.y - mu) * rstd * gg.y + bb.y;
            o.z = (xv.z - mu) * rstd * gg.z + bb.z;
            o.w = (xv.w - mu) * rstd * gg.w + bb.w;
            xnr[i4] = o;
        }
    }

    // ---------- GEMM: [16 x 1024] x [1024 x 192] ----------
    const int cg = tid & 63;   // col group: cols 3*cg .. 3*cg+2
    const int rg = tid >> 6;   // row group: rows 4*rg .. 4*rg+3

    float acc[4][3];
    #pragma unroll
    for (int j = 0; j < 4; j++)
        #pragma unroll
        for (int i = 0; i < 3; i++) acc[j][i] = 0.f;

    for (int ch = 0; ch < EMB / K1_KC; ch++) {
        const int k0 = ch * K1_KC;
        __syncthreads();  // protect wch from readers of previous chunk
        // stage weight chunk [192][32]
        for (int idx = tid; idx < 192 * K1_KC; idx += 256) {
            const int c  = idx >> 5;
            const int kk = idx & 31;
            const float* Wr = (c < 64) ? (Wq + c * EMB)
                            : (c < 128) ? (Wk + (c - 64) * EMB)
                            : (Wv + (c - 128) * EMB);
            wch[c * K1_WPAD + kk] = Wr[k0 + kk];
        }
        __syncthreads();

        #pragma unroll
        for (int kk = 0; kk < K1_KC; kk += 4) {
            float4 xv[4];
            #pragma unroll
            for (int j = 0; j < 4; j++)
                xv[j] = *(const float4*)(xn + (rg * 4 + j) * EMB + k0 + kk);
            #pragma unroll
            for (int i = 0; i < 3; i++) {
                const float4 wv = *(const float4*)(wch + (3 * cg + i) * K1_WPAD + kk);
                #pragma unroll
                for (int j = 0; j < 4; j++)
                    acc[j][i] += xv[j].x * wv.x + xv[j].y * wv.y
                               + xv[j].z * wv.z + xv[j].w * wv.w;
            }
        }
    }

    // ---------- scatter to g_q / g_k / g_v ----------
    #pragma unroll
    for (int j = 0; j < 4; j++) {
        const int grow = rowBase + rg * 4 + j;
        #pragma unroll
        for (int i = 0; i < 3; i++) {
            const int c = 3 * cg + i;
            float* dst = (c < 64)  ? (g_q + grow * HEAD + c)
                       : (c < 128) ? (g_k + grow * HEAD + (c - 64))
                                   : (g_v + grow * HEAD + (c - 128));
            *dst = acc[j][i];
        }
    }
}

// ================= Kernel 2: causal flash attention =================
// BQ=32, BK=64. 128 blocks; block (b, pair) processes q-tiles {pair, 63-pair}
// within batch b -> every block does exactly 65 KV-tile-units of 32 queries.
#define BQ 32
#define BK 64
#define KPAD 68
// smem: q[32*64] + k[64*68] + v[64*68] + p[32*68] + m/l/corr[3*32]
#define K2_SMEM ((BQ*HEAD + 2*BK*KPAD + BQ*KPAD + 3*BQ) * sizeof(float))

__global__ void __launch_bounds__(256, 1)
attn_kernel(float* __restrict__ out)
{
    extern __shared__ float sm2[];
    float* q_s = sm2;                          // [32][64]
    float* k_s = q_s + BQ * HEAD;              // [64][68]
    float* v_s = k_s + BK * KPAD;              // [64][68]
    float* p_s = v_s + BK * KPAD;              // [32][68]
    float* m_s = p_s + BQ * KPAD;              // [32]
    float* l_s = m_s + BQ;                     // [32]
    float* c_s = l_s + BQ;                     // [32]

    const int tid = threadIdx.x;
    const int b    = blockIdx.x >> 5;
    const int pair = blockIdx.x & 31;

    const float* Q = g_q + (size_t)b * SEQ * HEAD;
    const float* K = g_k + (size_t)b * SEQ * HEAD;
    const float* V = g_v + (size_t)b * SEQ * HEAD;
    float* O = out + (size_t)b * SEQ * HEAD;

    const int rg = tid >> 4;   // 0..15: rows 2*rg, 2*rg+1
    const int cg = tid & 15;   // 0..15

    for (int which = 0; which < 2; which++) {
        const int qt = which ? (63 - pair) : pair;
        const int qbase = qt * BQ;
        const int nkv = (qbase + BQ + BK - 1) / BK;

        // load Q tile (pre-scaled by 1/sqrt(64))
        for (int i = tid; i < BQ * HEAD; i += 256)
            q_s[i] = Q[qbase * HEAD + i] * 0.125f;
        if (tid < BQ) { m_s[tid] = -1e30f; l_s[tid] = 0.f; }

        float acc[2][4] = {{0.f,0.f,0.f,0.f},{0.f,0.f,0.f,0.f}};
        __syncthreads();

        for (int t = 0; t < nkv; t++) {
            const int kb = t * BK;
            // stage K/V tiles (float4, coalesced)
            const float4* K4 = (const float4*)K + kb * (HEAD / 4);
            const float4* V4 = (const float4*)V + kb * (HEAD / 4);
            for (int i = tid; i < BK * (HEAD / 4); i += 256) {
                const int row = i >> 4, c4 = i & 15;
                ((float4*)(k_s + row * KPAD))[c4] = K4[i];
                ((float4*)(v_s + row * KPAD))[c4] = V4[i];
            }
            __syncthreads();

            // S = Q K^T  (thread: 2 q-rows x 4 key-cols spaced 16)
            float s[2][4] = {{0.f,0.f,0.f,0.f},{0.f,0.f,0.f,0.f}};
            #pragma unroll
            for (int kk = 0; kk < HEAD; kk += 4) {
                const float4 q0 = *(const float4*)(q_s + (2*rg)   * HEAD + kk);
                const float4 q1 = *(const float4*)(q_s + (2*rg+1) * HEAD + kk);
                #pragma unroll
                for (int i = 0; i < 4; i++) {
                    const float4 kv = *(const float4*)(k_s + (cg + 16*i) * KPAD + kk);
                    s[0][i] += q0.x*kv.x + q0.y*kv.y + q0.z*kv.z + q0.w*kv.w;
                    s[1][i] += q1.x*kv.x + q1.y*kv.y + q1.z*kv.z + q1.w*kv.w;
                }
            }
            // causal mask + store scores
            #pragma unroll
            for (int j = 0; j < 2; j++) {
                const int qg = qbase + 2*rg + j;
                #pragma unroll
                for (int i = 0; i < 4; i++) {
                    const int kg = kb + cg + 16*i;
                    p_s[(2*rg + j) * KPAD + cg + 16*i] = (kg <= qg) ? s[j][i] : -1e30f;
                }
            }
            __syncthreads();

            // online softmax: 8 threads per row
            {
                const int row = tid >> 3, tr = tid & 7;
                float mx = -1e30f;
                #pragma unroll
                for (int u = 0; u < 8; u++)
                    mx = fmaxf(mx, p_s[row * KPAD + tr + 8*u]);
                #pragma unroll
                for (int off = 4; off; off >>= 1)
                    mx = fmaxf(mx, __shfl_xor_sync(0xffffffffu, mx, off));
                const float m_old = m_s[row];
                const float m_new = fmaxf(m_old, mx);
                const float corr  = __expf(m_old - m_new);
                float lsum = 0.f;
                #pragma unroll
                for (int u = 0; u < 8; u++) {
                    const int idx = row * KPAD + tr + 8*u;
                    const float e = __expf(p_s[idx] - m_new);
                    p_s[idx] = e;
                    lsum += e;
                }
                #pragma unroll
                for (int off = 4; off; off >>= 1)
                    lsum += __shfl_xor_sync(0xffffffffu, lsum, off);
                if (tr == 0) {
                    l_s[row] = l_s[row] * corr + lsum;
                    m_s[row] = m_new;
                    c_s[row] = corr;
                }
            }
            __syncthreads();

            // rescale accumulators, then O += P V  (cols = 4*cg..4*cg+3 contiguous)
            const float c0 = c_s[2*rg], c1 = c_s[2*rg + 1];
            #pragma unroll
            for (int i = 0; i < 4; i++) { acc[0][i] *= c0; acc[1][i] *= c1; }
            #pragma unroll
            for (int kk = 0; kk < BK; kk += 4) {
                const float4 p0 = *(const float4*)(p_s + (2*rg)   * KPAD + kk);
                const float4 p1 = *(const float4*)(p_s + (2*rg+1) * KPAD + kk);
                #pragma unroll
                for (int u = 0; u < 4; u++) {
                    const float4 vv = *(const float4*)(v_s + (kk + u) * KPAD + 4*cg);
                    const float a0 = (&p0.x)[u];
                    const float a1 = (&p1.x)[u];
                    acc[0][0] += a0 * vv.x; acc[0][1] += a0 * vv.y;
                    acc[0][2] += a0 * vv.z; acc[0][3] += a0 * vv.w;
                    acc[1][0] += a1 * vv.x; acc[1][1] += a1 * vv.y;
                    acc[1][2] += a1 * vv.z; acc[1][3] += a1 * vv.w;
                }
            }
            __syncthreads();
        }

        // write output
        #pragma unroll
        for (int j = 0; j < 2; j++) {
            const int qg = qbase + 2*rg + j;
            const float invl = 1.0f / l_s[2*rg + j];
            float4 o;
            o.x = acc[j][0] * invl; o.y = acc[j][1] * invl;
            o.z = acc[j][2] * invl; o.w = acc[j][3] * invl;
            *(float4*)(O + (size_t)qg * HEAD + 4*cg) = o;
        }
        __syncthreads();  // before overwriting q_s / m_s / l_s for 2nd tile
    }
}

// ================= launch =================
extern "C" void kernel_launch(void* const* d_in, const int* in_sizes, int n_in,
                              void* d_out, int out_size)
{
    const float* x     = (const float*)d_in[0];
    const float* gamma = (const float*)d_in[1];
    const float* beta  = (const float*)d_in[2];
    const float* Wq    = (const float*)d_in[3];
    const float* Wk    = (const float*)d_in[4];
    const float* Wv    = (const float*)d_in[5];
    float* out = (float*)d_out;

    cudaFuncSetAttribute(ln_qkv_kernel, cudaFuncAttributeMaxDynamicSharedMemorySize, (int)K1_SMEM);
    cudaFuncSetAttribute(attn_kernel,   cudaFuncAttributeMaxDynamicSharedMemorySize, (int)K2_SMEM);

    ln_qkv_kernel<<<NROWS / K1_ROWS, 256, K1_SMEM>>>(x, gamma, beta, Wq, Wk, Wv);
    attn_kernel<<<BATCH * 32, 256, K2_SMEM>>>(out);
}

// round 3
// speedup vs baseline: 3.0905x; 3.0905x over previous
#include <cuda_runtime.h>
#include <cuda_bf16.h>
#include <stdint.h>
#include <math.h>

// Problem constants
#define BATCH 4
#define SEQ   2048
#define EMB   1024
#define HEAD  64
#define NROWS (BATCH * SEQ)   // 8192

// ---------------- scratch (q, k, v projections) ----------------
__device__ float g_q[NROWS * HEAD];
__device__ float g_k[NROWS * HEAD];
__device__ float g_v[NROWS * HEAD];

// ================= Kernel 1: LayerNorm + QKV projection (tf32 tensor cores) ===
// Block: M=64 rows x N=192 cols, K=1024 in chunks of 64. 256 threads = 8 warps.
// Warp grid 2(m) x 4(n): warp tile 32x48 = 12 mma.m16n8k8 atoms.
#define K1_TM 64
#define K1_KC 64
#define ASTR 68   // 68 mod 32 = 4 -> bank(A frag) = 4*grp + tig : conflict-free
#define BSTR 68   // B stored n-major [192][68]; bank(B frag) = 4*grp + tig
// smem: A[64*68] + B[192*68] + mu[64] + rstd[64]
#define K1_SMEM ((K1_TM*ASTR + 192*BSTR + 128) * sizeof(float))

__device__ __forceinline__ uint32_t f2tf32(float f) {
    uint32_t r;
    asm("cvt.rna.tf32.f32 %0, %1;" : "=r"(r) : "f"(f));
    return r;
}

__device__ __forceinline__ void mma_tf32(float* d, const uint32_t* a,
                                         uint32_t b0, uint32_t b1) {
    asm volatile(
        "mma.sync.aligned.m16n8k8.row.col.f32.tf32.tf32.f32 "
        "{%0,%1,%2,%3}, {%4,%5,%6,%7}, {%8,%9}, {%0,%1,%2,%3};"
        : "+f"(d[0]), "+f"(d[1]), "+f"(d[2]), "+f"(d[3])
        : "r"(a[0]), "r"(a[1]), "r"(a[2]), "r"(a[3]), "r"(b0), "r"(b1));
}

__global__ void __launch_bounds__(256, 2)
ln_qkv_kernel(const float* __restrict__ x,
              const float* __restrict__ gamma,
              const float* __restrict__ beta,
              const float* __restrict__ Wq,
              const float* __restrict__ Wk,
              const float* __restrict__ Wv)
{
    extern __shared__ float sm1[];
    float* A_s  = sm1;                       // [64][68] tf32 bits
    float* B_s  = sm1 + K1_TM * ASTR;        // [192][68] tf32 bits (n-major)
    float* mu_s = B_s + 192 * BSTR;          // [64]
    float* rs_s = mu_s + 64;                 // [64]

    const int tid  = threadIdx.x;
    const int warp = tid >> 5;
    const int lane = tid & 31;
    const int rowBase = blockIdx.x * K1_TM;

    // ---------- LayerNorm stats: warp w handles rows 8w..8w+7 ----------
    #pragma unroll
    for (int rr = 0; rr < 8; rr++) {
        const int r = warp * 8 + rr;
        const float4* xr = (const float4*)(x + (size_t)(rowBase + r) * EMB);
        float sum = 0.f, sq = 0.f;
        #pragma unroll
        for (int t = 0; t < 8; t++) {
            float4 v = xr[lane + 32 * t];
            sum += v.x + v.y + v.z + v.w;
            sq  += v.x*v.x + v.y*v.y + v.z*v.z + v.w*v.w;
        }
        #pragma unroll
        for (int off = 16; off; off >>= 1) {
            sum += __shfl_xor_sync(0xffffffffu, sum, off);
            sq  += __shfl_xor_sync(0xffffffffu, sq,  off);
        }
        if (lane == 0) {
            const float inv = 1.0f / (float)EMB;
            const float mu = sum * inv;
            const float var = sq * inv - mu * mu;
            mu_s[r] = mu;
            rs_s[r] = rsqrtf(var + 1e-5f);
        }
    }
    __syncthreads();

    const int wm  = warp >> 2;   // 0..1
    const int wn  = warp & 3;    // 0..3
    const int grp = lane >> 2;   // 0..7
    const int tig = lane & 3;    // 0..3

    float acc[12][4];
    #pragma unroll
    for (int i = 0; i < 12; i++)
        #pragma unroll
        for (int j = 0; j < 4; j++) acc[i][j] = 0.f;

    for (int ch = 0; ch < EMB / K1_KC; ch++) {
        const int k0 = ch * K1_KC;
        __syncthreads();

        // ---- stage A: normalize x chunk [64][64] -> tf32 ----
        #pragma unroll
        for (int j = 0; j < 4; j++) {
            const int idx = tid + 256 * j;        // 0..1023
            const int row = idx >> 4;
            const int kg  = idx & 15;
            const float4 xv = *(const float4*)(x + (size_t)(rowBase + row) * EMB + k0 + kg * 4);
            const float4 gg = *(const float4*)(gamma + k0 + kg * 4);
            const float4 bb = *(const float4*)(beta  + k0 + kg * 4);
            const float mu = mu_s[row], rs = rs_s[row];
            float4 o;
            o.x = __uint_as_float(f2tf32((xv.x - mu) * rs * gg.x + bb.x));
            o.y = __uint_as_float(f2tf32((xv.y - mu) * rs * gg.y + bb.y));
            o.z = __uint_as_float(f2tf32((xv.z - mu) * rs * gg.z + bb.z));
            o.w = __uint_as_float(f2tf32((xv.w - mu) * rs * gg.w + bb.w));
            *(float4*)(A_s + row * ASTR + kg * 4) = o;
        }
        // ---- stage B: weight chunk [192][64] -> tf32, n-major ----
        #pragma unroll
        for (int j = 0; j < 12; j++) {
            const int idx = tid + 256 * j;        // 0..3071
            const int c   = idx >> 4;
            const int kg  = idx & 15;
            const float* Wr = (c < 64)  ? (Wq + (size_t)c * EMB)
                            : (c < 128) ? (Wk + (size_t)(c - 64) * EMB)
                                        : (Wv + (size_t)(c - 128) * EMB);
            const float4 wv = *(const float4*)(Wr + k0 + kg * 4);
            float4 o;
            o.x = __uint_as_float(f2tf32(wv.x));
            o.y = __uint_as_float(f2tf32(wv.y));
            o.z = __uint_as_float(f2tf32(wv.z));
            o.w = __uint_as_float(f2tf32(wv.w));
            *(float4*)(B_s + c * BSTR + kg * 4) = o;
        }
        __syncthreads();

        // ---- 8 k8-steps of mma ----
        #pragma unroll
        for (int k8 = 0; k8 < 8; k8++) {
            const int kk = k8 * 8;
            uint32_t a[2][4];
            #pragma unroll
            for (int tm = 0; tm < 2; tm++) {
                const int rr = wm * 32 + tm * 16 + grp;
                a[tm][0] = __float_as_uint(A_s[rr * ASTR + kk + tig]);
                a[tm][1] = __float_as_uint(A_s[(rr + 8) * ASTR + kk + tig]);
                a[tm][2] = __float_as_uint(A_s[rr * ASTR + kk + tig + 4]);
                a[tm][3] = __float_as_uint(A_s[(rr + 8) * ASTR + kk + tig + 4]);
            }
            #pragma unroll
            for (int tn = 0; tn < 6; tn++) {
                const int bc = wn * 48 + tn * 8 + grp;
                const uint32_t b0 = __float_as_uint(B_s[bc * BSTR + kk + tig]);
                const uint32_t b1 = __float_as_uint(B_s[bc * BSTR + kk + tig + 4]);
                mma_tf32(acc[0 * 6 + tn], a[0], b0, b1);
                mma_tf32(acc[1 * 6 + tn], a[1], b0, b1);
            }
        }
    }

    // ---------- epilogue: scatter to g_q / g_k / g_v ----------
    #pragma unroll
    for (int tm = 0; tm < 2; tm++) {
        #pragma unroll
        for (int tn = 0; tn < 6; tn++) {
            const int i = tm * 6 + tn;
            const int r0 = rowBase + wm * 32 + tm * 16 + grp;
            const int c  = wn * 48 + tn * 8 + tig * 2;
            float* dst = (c < 64)  ? (g_q + (size_t)r0 * HEAD + c)
                       : (c < 128) ? (g_k + (size_t)r0 * HEAD + (c - 64))
                                   : (g_v + (size_t)r0 * HEAD + (c - 128));
            *(float2*)dst = make_float2(acc[i][0], acc[i][1]);
            *(float2*)(dst + 8 * HEAD) = make_float2(acc[i][2], acc[i][3]);
        }
    }
}

// ================= Kernel 2: causal flash attention =================
// BQ=32, BK=64. 128 blocks; block (b, pair) processes q-tiles {pair, 63-pair}
// within batch b -> every block does exactly 65 KV-tile-units of 32 queries.
#define BQ 32
#define BK 64
#define KPAD 68
// smem: q[32*64] + k[64*68] + v[64*68] + p[32*68] + m/l/corr[3*32]
#define K2_SMEM ((BQ*HEAD + 2*BK*KPAD + BQ*KPAD + 3*BQ) * sizeof(float))

__global__ void __launch_bounds__(256, 1)
attn_kernel(float* __restrict__ out)
{
    extern __shared__ float sm2[];
    float* q_s = sm2;                          // [32][64]
    float* k_s = q_s + BQ * HEAD;              // [64][68]
    float* v_s = k_s + BK * KPAD;              // [64][68]
    float* p_s = v_s + BK * KPAD;              // [32][68]
    float* m_s = p_s + BQ * KPAD;              // [32]
    float* l_s = m_s + BQ;                     // [32]
    float* c_s = l_s + BQ;                     // [32]

    const int tid = threadIdx.x;
    const int b    = blockIdx.x >> 5;
    const int pair = blockIdx.x & 31;

    const float* Q = g_q + (size_t)b * SEQ * HEAD;
    const float* K = g_k + (size_t)b * SEQ * HEAD;
    const float* V = g_v + (size_t)b * SEQ * HEAD;
    float* O = out + (size_t)b * SEQ * HEAD;

    const int rg = tid >> 4;   // 0..15: rows 2*rg, 2*rg+1
    const int cg = tid & 15;   // 0..15

    for (int which = 0; which < 2; which++) {
        const int qt = which ? (63 - pair) : pair;
        const int qbase = qt * BQ;
        const int nkv = (qbase + BQ + BK - 1) / BK;

        // load Q tile (pre-scaled by 1/sqrt(64))
        for (int i = tid; i < BQ * HEAD; i += 256)
            q_s[i] = Q[qbase * HEAD + i] * 0.125f;
        if (tid < BQ) { m_s[tid] = -1e30f; l_s[tid] = 0.f; }

        float acc[2][4] = {{0.f,0.f,0.f,0.f},{0.f,0.f,0.f,0.f}};
        __syncthreads();

        for (int t = 0; t < nkv; t++) {
            const int kb = t * BK;
            // stage K/V tiles (float4, coalesced)
            const float4* K4 = (const float4*)K + kb * (HEAD / 4);
            const float4* V4 = (const float4*)V + kb * (HEAD / 4);
            for (int i = tid; i < BK * (HEAD / 4); i += 256) {
                const int row = i >> 4, c4 = i & 15;
                ((float4*)(k_s + row * KPAD))[c4] = K4[i];
                ((float4*)(v_s + row * KPAD))[c4] = V4[i];
            }
            __syncthreads();

            // S = Q K^T  (thread: 2 q-rows x 4 key-cols spaced 16)
            float s[2][4] = {{0.f,0.f,0.f,0.f},{0.f,0.f,0.f,0.f}};
            #pragma unroll
            for (int kk = 0; kk < HEAD; kk += 4) {
                const float4 q0 = *(const float4*)(q_s + (2*rg)   * HEAD + kk);
                const float4 q1 = *(const float4*)(q_s + (2*rg+1) * HEAD + kk);
                #pragma unroll
                for (int i = 0; i < 4; i++) {
                    const float4 kv = *(const float4*)(k_s + (cg + 16*i) * KPAD + kk);
                    s[0][i] += q0.x*kv.x + q0.y*kv.y + q0.z*kv.z + q0.w*kv.w;
                    s[1][i] += q1.x*kv.x + q1.y*kv.y + q1.z*kv.z + q1.w*kv.w;
                }
            }
            // causal mask + store scores
            #pragma unroll
            for (int j = 0; j < 2; j++) {
                const int qg = qbase + 2*rg + j;
                #pragma unroll
                for (int i = 0; i < 4; i++) {
                    const int kg = kb + cg + 16*i;
                    p_s[(2*rg + j) * KPAD + cg + 16*i] = (kg <= qg) ? s[j][i] : -1e30f;
                }
            }
            __syncthreads();

            // online softmax: 8 threads per row
            {
                const int row = tid >> 3, tr = tid & 7;
                float mx = -1e30f;
                #pragma unroll
                for (int u = 0; u < 8; u++)
                    mx = fmaxf(mx, p_s[row * KPAD + tr + 8*u]);
                #pragma unroll
                for (int off = 4; off; off >>= 1)
                    mx = fmaxf(mx, __shfl_xor_sync(0xffffffffu, mx, off));
                const float m_old = m_s[row];
                const float m_new = fmaxf(m_old, mx);
                const float corr  = __expf(m_old - m_new);
                float lsum = 0.f;
                #pragma unroll
                for (int u = 0; u < 8; u++) {
                    const int idx = row * KPAD + tr + 8*u;
                    const float e = __expf(p_s[idx] - m_new);
                    p_s[idx] = e;
                    lsum += e;
                }
                #pragma unroll
                for (int off = 4; off; off >>= 1)
                    lsum += __shfl_xor_sync(0xffffffffu, lsum, off);
                if (tr == 0) {
                    l_s[row] = l_s[row] * corr + lsum;
                    m_s[row] = m_new;
                    c_s[row] = corr;
                }
            }
            __syncthreads();

            // rescale accumulators, then O += P V  (cols = 4*cg..4*cg+3 contiguous)
            const float c0 = c_s[2*rg], c1 = c_s[2*rg + 1];
            #pragma unroll
            for (int i = 0; i < 4; i++) { acc[0][i] *= c0; acc[1][i] *= c1; }
            #pragma unroll
            for (int kk = 0; kk < BK; kk += 4) {
                const float4 p0 = *(const float4*)(p_s + (2*rg)   * KPAD + kk);
                const float4 p1 = *(const float4*)(p_s + (2*rg+1) * KPAD + kk);
                #pragma unroll
                for (int u = 0; u < 4; u++) {
                    const float4 vv = *(const float4*)(v_s + (kk + u) * KPAD + 4*cg);
                    const float a0 = (&p0.x)[u];
                    const float a1 = (&p1.x)[u];
                    acc[0][0] += a0 * vv.x; acc[0][1] += a0 * vv.y;
                    acc[0][2] += a0 * vv.z; acc[0][3] += a0 * vv.w;
                    acc[1][0] += a1 * vv.x; acc[1][1] += a1 * vv.y;
                    acc[1][2] += a1 * vv.z; acc[1][3] += a1 * vv.w;
                }
            }
            __syncthreads();
        }

        // write output
        #pragma unroll
        for (int j = 0; j < 2; j++) {
            const int qg = qbase + 2*rg + j;
            const float invl = 1.0f / l_s[2*rg + j];
            float4 o;
            o.x = acc[j][0] * invl; o.y = acc[j][1] * invl;
            o.z = acc[j][2] * invl; o.w = acc[j][3] * invl;
            *(float4*)(O + (size_t)qg * HEAD + 4*cg) = o;
        }
        __syncthreads();  // before overwriting q_s / m_s / l_s for 2nd tile
    }
}

// ================= launch =================
extern "C" void kernel_launch(void* const* d_in, const int* in_sizes, int n_in,
                              void* d_out, int out_size)
{
    const float* x     = (const float*)d_in[0];
    const float* gamma = (const float*)d_in[1];
    const float* beta  = (const float*)d_in[2];
    const float* Wq    = (const float*)d_in[3];
    const float* Wk    = (const float*)d_in[4];
    const float* Wv    = (const float*)d_in[5];
    float* out = (float*)d_out;

    cudaFuncSetAttribute(ln_qkv_kernel, cudaFuncAttributeMaxDynamicSharedMemorySize, (int)K1_SMEM);
    cudaFuncSetAttribute(attn_kernel,   cudaFuncAttributeMaxDynamicSharedMemorySize, (int)K2_SMEM);

    ln_qkv_kernel<<<NROWS / K1_TM, 256, K1_SMEM>>>(x, gamma, beta, Wq, Wk, Wv);
    attn_kernel<<<BATCH * 32, 256, K2_SMEM>>>(out);
}

// round 4
// speedup vs baseline: 5.0721x; 1.6412x over previous
#include <cuda_runtime.h>
#include <cuda_bf16.h>
#include <stdint.h>
#include <math.h>

// Problem constants
#define BATCH 4
#define SEQ   2048
#define EMB   1024
#define HEAD  64
#define NROWS (BATCH * SEQ)   // 8192

// ---------------- scratch (q, k, v projections) ----------------
__device__ float g_q[NROWS * HEAD];
__device__ float g_k[NROWS * HEAD];
__device__ float g_v[NROWS * HEAD];

__device__ __forceinline__ uint32_t f2tf32(float f) {
    uint32_t r;
    asm("cvt.rna.tf32.f32 %0, %1;" : "=r"(r) : "f"(f));
    return r;
}

__device__ __forceinline__ void mma_tf32(float* d, const uint32_t* a,
                                         uint32_t b0, uint32_t b1) {
    asm volatile(
        "mma.sync.aligned.m16n8k8.row.col.f32.tf32.tf32.f32 "
        "{%0,%1,%2,%3}, {%4,%5,%6,%7}, {%8,%9}, {%0,%1,%2,%3};"
        : "+f"(d[0]), "+f"(d[1]), "+f"(d[2]), "+f"(d[3])
        : "r"(a[0]), "r"(a[1]), "r"(a[2]), "r"(a[3]), "r"(b0), "r"(b1));
}

__device__ __forceinline__ uint32_t smem_u32(const void* p) {
    return (uint32_t)__cvta_generic_to_shared(p);
}

#define CP_ASYNC16(dst_u32, src_ptr) \
    asm volatile("cp.async.cg.shared.global [%0], [%1], 16;" \
                 :: "r"(dst_u32), "l"(src_ptr))
#define CP_COMMIT() asm volatile("cp.async.commit_group;")
#define CP_WAIT(N)  asm volatile("cp.async.wait_group %0;" :: "n"(N))

// ================= Kernel 1: LayerNorm + QKV projection (tf32 tensor cores) ===
#define K1_TM 64
#define K1_KC 64
#define ASTR 68
#define BSTR 68
#define K1_SMEM ((K1_TM*ASTR + 192*BSTR + 128) * sizeof(float))

__global__ void __launch_bounds__(256, 2)
ln_qkv_kernel(const float* __restrict__ x,
              const float* __restrict__ gamma,
              const float* __restrict__ beta,
              const float* __restrict__ Wq,
              const float* __restrict__ Wk,
              const float* __restrict__ Wv)
{
    extern __shared__ float sm1[];
    float* A_s  = sm1;                       // [64][68]
    float* B_s  = sm1 + K1_TM * ASTR;        // [192][68]
    float* mu_s = B_s + 192 * BSTR;          // [64]
    float* rs_s = mu_s + 64;                 // [64]

    const int tid  = threadIdx.x;
    const int warp = tid >> 5;
    const int lane = tid & 31;
    const int rowBase = blockIdx.x * K1_TM;

    #pragma unroll
    for (int rr = 0; rr < 8; rr++) {
        const int r = warp * 8 + rr;
        const float4* xr = (const float4*)(x + (size_t)(rowBase + r) * EMB);
        float sum = 0.f, sq = 0.f;
        #pragma unroll
        for (int t = 0; t < 8; t++) {
            float4 v = xr[lane + 32 * t];
            sum += v.x + v.y + v.z + v.w;
            sq  += v.x*v.x + v.y*v.y + v.z*v.z + v.w*v.w;
        }
        #pragma unroll
        for (int off = 16; off; off >>= 1) {
            sum += __shfl_xor_sync(0xffffffffu, sum, off);
            sq  += __shfl_xor_sync(0xffffffffu, sq,  off);
        }
        if (lane == 0) {
            const float inv = 1.0f / (float)EMB;
            const float mu = sum * inv;
            const float var = sq * inv - mu * mu;
            mu_s[r] = mu;
            rs_s[r] = rsqrtf(var + 1e-5f);
        }
    }
    __syncthreads();

    const int wm  = warp >> 2;
    const int wn  = warp & 3;
    const int grp = lane >> 2;
    const int tig = lane & 3;

    float acc[12][4];
    #pragma unroll
    for (int i = 0; i < 12; i++)
        #pragma unroll
        for (int j = 0; j < 4; j++) acc[i][j] = 0.f;

    for (int ch = 0; ch < EMB / K1_KC; ch++) {
        const int k0 = ch * K1_KC;
        __syncthreads();

        #pragma unroll
        for (int j = 0; j < 4; j++) {
            const int idx = tid + 256 * j;
            const int row = idx >> 4;
            const int kg  = idx & 15;
            const float4 xv = *(const float4*)(x + (size_t)(rowBase + row) * EMB + k0 + kg * 4);
            const float4 gg = *(const float4*)(gamma + k0 + kg * 4);
            const float4 bb = *(const float4*)(beta  + k0 + kg * 4);
            const float mu = mu_s[row], rs = rs_s[row];
            float4 o;
            o.x = __uint_as_float(f2tf32((xv.x - mu) * rs * gg.x + bb.x));
            o.y = __uint_as_float(f2tf32((xv.y - mu) * rs * gg.y + bb.y));
            o.z = __uint_as_float(f2tf32((xv.z - mu) * rs * gg.z + bb.z));
            o.w = __uint_as_float(f2tf32((xv.w - mu) * rs * gg.w + bb.w));
            *(float4*)(A_s + row * ASTR + kg * 4) = o;
        }
        #pragma unroll
        for (int j = 0; j < 12; j++) {
            const int idx = tid + 256 * j;
            const int c   = idx >> 4;
            const int kg  = idx & 15;
            const float* Wr = (c < 64)  ? (Wq + (size_t)c * EMB)
                            : (c < 128) ? (Wk + (size_t)(c - 64) * EMB)
                                        : (Wv + (size_t)(c - 128) * EMB);
            const float4 wv = *(const float4*)(Wr + k0 + kg * 4);
            float4 o;
            o.x = __uint_as_float(f2tf32(wv.x));
            o.y = __uint_as_float(f2tf32(wv.y));
            o.z = __uint_as_float(f2tf32(wv.z));
            o.w = __uint_as_float(f2tf32(wv.w));
            *(float4*)(B_s + c * BSTR + kg * 4) = o;
        }
        __syncthreads();

        #pragma unroll
        for (int k8 = 0; k8 < 8; k8++) {
            const int kk = k8 * 8;
            uint32_t a[2][4];
            #pragma unroll
            for (int tm = 0; tm < 2; tm++) {
                const int rr = wm * 32 + tm * 16 + grp;
                a[tm][0] = __float_as_uint(A_s[rr * ASTR + kk + tig]);
                a[tm][1] = __float_as_uint(A_s[(rr + 8) * ASTR + kk + tig]);
                a[tm][2] = __float_as_uint(A_s[rr * ASTR + kk + tig + 4]);
                a[tm][3] = __float_as_uint(A_s[(rr + 8) * ASTR + kk + tig + 4]);
            }
            #pragma unroll
            for (int tn = 0; tn < 6; tn++) {
                const int bc = wn * 48 + tn * 8 + grp;
                const uint32_t b0 = __float_as_uint(B_s[bc * BSTR + kk + tig]);
                const uint32_t b1 = __float_as_uint(B_s[bc * BSTR + kk + tig + 4]);
                mma_tf32(acc[0 * 6 + tn], a[0], b0, b1);
                mma_tf32(acc[1 * 6 + tn], a[1], b0, b1);
            }
        }
    }

    #pragma unroll
    for (int tm = 0; tm < 2; tm++) {
        #pragma unroll
        for (int tn = 0; tn < 6; tn++) {
            const int i = tm * 6 + tn;
            const int r0 = rowBase + wm * 32 + tm * 16 + grp;
            const int c  = wn * 48 + tn * 8 + tig * 2;
            float* dst = (c < 64)  ? (g_q + (size_t)r0 * HEAD + c)
                       : (c < 128) ? (g_k + (size_t)r0 * HEAD + (c - 64))
                                   : (g_v + (size_t)r0 * HEAD + (c - 128));
            *(float2*)dst = make_float2(acc[i][0], acc[i][1]);
            *(float2*)(dst + 8 * HEAD) = make_float2(acc[i][2], acc[i][3]);
        }
    }
}

// ================= Kernel 2: causal flash attention (tf32 mma) =================
// BQ=64, BK=64. Grid = 4 batches x 32 q-tiles = 128 blocks, 128 threads (4 warps).
// Warp w owns q-rows [qbase + 16w, qbase + 16w + 15], full 64-key width.
// Softmax stats live in registers (quad shuffles). K/V double-buffered via cp.async.
#define QSTR 68   // banks: 4*grp + tig  -> conflict-free A/B row-indexed frags
#define KSTR 68
#define VSTR 72   // banks: 8*tig + grp  -> conflict-free V frags
// smem floats: q[64*68] + k[2][64*68] + v[2][64*72]
#define K2_SMEM ((64*QSTR + 2*64*KSTR + 2*64*VSTR) * sizeof(float))

__global__ void __launch_bounds__(128)
attn_mma_kernel(float* __restrict__ out)
{
    extern __shared__ float sm2[];
    float* q_s = sm2;                       // [64][68]
    float* k_s = q_s + 64 * QSTR;           // [2][64][68]
    float* v_s = k_s + 2 * 64 * KSTR;       // [2][64][72]

    const int tid  = threadIdx.x;
    const int warp = tid >> 5;
    const int lane = tid & 31;
    const int grp  = lane >> 2;   // 0..7
    const int tig  = lane & 3;    // 0..3

    const int b  = blockIdx.x >> 5;
    const int qt = blockIdx.x & 31;
    const int qbase = qt * 64;
    const int nkv = qt + 1;

    const float* Q = g_q + (size_t)b * SEQ * HEAD + (size_t)qbase * HEAD;
    const float* K = g_k + (size_t)b * SEQ * HEAD;
    const float* V = g_v + (size_t)b * SEQ * HEAD;
    float* O = out + (size_t)b * SEQ * HEAD;

    const uint32_t q_u = smem_u32(q_s);
    const uint32_t k_u = smem_u32(k_s);
    const uint32_t v_u = smem_u32(v_s);

    // ---- stage Q (cp.async) + prefetch KV tile 0 ----
    {
        #pragma unroll
        for (int i = 0; i < 8; i++) {
            const int idx = tid + 128 * i;
            const int row = idx >> 4, c4 = idx & 15;
            CP_ASYNC16(q_u + (row * QSTR + c4 * 4) * 4, Q + row * HEAD + c4 * 4);
        }
        #pragma unroll
        for (int i = 0; i < 8; i++) {
            const int idx = tid + 128 * i;
            const int row = idx >> 4, c4 = idx & 15;
            CP_ASYNC16(k_u + (row * KSTR + c4 * 4) * 4, K + row * HEAD + c4 * 4);
            CP_ASYNC16(v_u + (row * VSTR + c4 * 4) * 4, V + row * HEAD + c4 * 4);
        }
        CP_COMMIT();
    }

    // wait for Q + tile 0, build Q fragments (pre-scaled by 1/sqrt(64))
    CP_WAIT(0);
    __syncthreads();

    uint32_t qa[8][4];
    {
        const int r0 = warp * 16 + grp;
        #pragma unroll
        for (int kc = 0; kc < 8; kc++) {
            const int kk = kc * 8;
            qa[kc][0] = f2tf32(0.125f * q_s[r0 * QSTR + kk + tig]);
            qa[kc][1] = f2tf32(0.125f * q_s[(r0 + 8) * QSTR + kk + tig]);
            qa[kc][2] = f2tf32(0.125f * q_s[r0 * QSTR + kk + tig + 4]);
            qa[kc][3] = f2tf32(0.125f * q_s[(r0 + 8) * QSTR + kk + tig + 4]);
        }
    }

    float o[8][4];
    #pragma unroll
    for (int nt = 0; nt < 8; nt++)
        #pragma unroll
        for (int j = 0; j < 4; j++) o[nt][j] = 0.f;
    float m0 = -1e30f, m1 = -1e30f, l0 = 0.f, l1 = 0.f;

    const int src_lo = (grp << 2) + (tig >> 1);
    const int src_hi = src_lo + 2;
    const int rl0 = warp * 16 + grp;       // local row of c0/c1
    const int rl1 = rl0 + 8;               // local row of c2/c3

    for (int t = 0; t < nkv; t++) {
        const int buf = t & 1;

        // prefetch tile t+1 into the other buffer
        if (t + 1 < nkv) {
            const int nb = (t + 1) & 1;
            const float* Kg = K + (size_t)(t + 1) * 64 * HEAD;
            const float* Vg = V + (size_t)(t + 1) * 64 * HEAD;
            #pragma unroll
            for (int i = 0; i < 8; i++) {
                const int idx = tid + 128 * i;
                const int row = idx >> 4, c4 = idx & 15;
                CP_ASYNC16(k_u + (nb * 64 * KSTR + row * KSTR + c4 * 4) * 4,
                           Kg + row * HEAD + c4 * 4);
                CP_ASYNC16(v_u + (nb * 64 * VSTR + row * VSTR + c4 * 4) * 4,
                           Vg + row * HEAD + c4 * 4);
            }
            CP_COMMIT();
            CP_WAIT(1);
        } else {
            CP_WAIT(0);
        }
        __syncthreads();

        const float* kb_s = k_s + buf * 64 * KSTR;
        const float* vb_s = v_s + buf * 64 * VSTR;

        // ---- S = Q K^T ----
        float s[8][4];
        #pragma unroll
        for (int nt = 0; nt < 8; nt++)
            #pragma unroll
            for (int j = 0; j < 4; j++) s[nt][j] = 0.f;

        #pragma unroll
        for (int kc = 0; kc < 8; kc++) {
            const int kk = kc * 8;
            #pragma unroll
            for (int nt = 0; nt < 8; nt++) {
                const int n = nt * 8 + grp;
                const uint32_t b0 = f2tf32(kb_s[n * KSTR + kk + tig]);
                const uint32_t b1 = f2tf32(kb_s[n * KSTR + kk + tig + 4]);
                mma_tf32(s[nt], qa[kc], b0, b1);
            }
        }

        // ---- causal mask on the diagonal tile ----
        if (t == qt) {
            #pragma unroll
            for (int nt = 0; nt < 8; nt++) {
                const int c0 = nt * 8 + 2 * tig;
                if (c0     > rl0) s[nt][0] = -1e30f;
                if (c0 + 1 > rl0) s[nt][1] = -1e30f;
                if (c0     > rl1) s[nt][2] = -1e30f;
                if (c0 + 1 > rl1) s[nt][3] = -1e30f;
            }
        }

        // ---- online softmax (register/quad only) ----
        float mx0 = -1e30f, mx1 = -1e30f;
        #pragma unroll
        for (int nt = 0; nt < 8; nt++) {
            mx0 = fmaxf(mx0, fmaxf(s[nt][0], s[nt][1]));
            mx1 = fmaxf(mx1, fmaxf(s[nt][2], s[nt][3]));
        }
        mx0 = fmaxf(mx0, __shfl_xor_sync(0xffffffffu, mx0, 1));
        mx0 = fmaxf(mx0, __shfl_xor_sync(0xffffffffu, mx0, 2));
        mx1 = fmaxf(mx1, __shfl_xor_sync(0xffffffffu, mx1, 1));
        mx1 = fmaxf(mx1, __shfl_xor_sync(0xffffffffu, mx1, 2));

        const float mn0 = fmaxf(m0, mx0);
        const float mn1 = fmaxf(m1, mx1);
        const float cor0 = __expf(m0 - mn0);
        const float cor1 = __expf(m1 - mn1);
        m0 = mn0; m1 = mn1;

        float sum0 = 0.f, sum1 = 0.f;
        #pragma unroll
        for (int nt = 0; nt < 8; nt++) {
            s[nt][0] = __expf(s[nt][0] - mn0);
            s[nt][1] = __expf(s[nt][1] - mn0);
            s[nt][2] = __expf(s[nt][2] - mn1);
            s[nt][3] = __expf(s[nt][3] - mn1);
            sum0 += s[nt][0] + s[nt][1];
            sum1 += s[nt][2] + s[nt][3];
        }
        sum0 += __shfl_xor_sync(0xffffffffu, sum0, 1);
        sum0 += __shfl_xor_sync(0xffffffffu, sum0, 2);
        sum1 += __shfl_xor_sync(0xffffffffu, sum1, 1);
        sum1 += __shfl_xor_sync(0xffffffffu, sum1, 2);
        l0 = l0 * cor0 + sum0;
        l1 = l1 * cor1 + sum1;

        #pragma unroll
        for (int nt = 0; nt < 8; nt++) {
            o[nt][0] *= cor0; o[nt][1] *= cor0;
            o[nt][2] *= cor1; o[nt][3] *= cor1;
        }

        // ---- P (C-frag) -> A-frag via quad shuffles ----
        uint32_t pa[8][4];
        #pragma unroll
        for (int kc = 0; kc < 8; kc++) {
            const float v0 = __shfl_sync(0xffffffffu, s[kc][0], src_lo);
            const float v1 = __shfl_sync(0xffffffffu, s[kc][1], src_lo);
            const float v2 = __shfl_sync(0xffffffffu, s[kc][2], src_lo);
            const float v3 = __shfl_sync(0xffffffffu, s[kc][3], src_lo);
            const float w0 = __shfl_sync(0xffffffffu, s[kc][0], src_hi);
            const float w1 = __shfl_sync(0xffffffffu, s[kc][1], src_hi);
            const float w2 = __shfl_sync(0xffffffffu, s[kc][2], src_hi);
            const float w3 = __shfl_sync(0xffffffffu, s[kc][3], src_hi);
            pa[kc][0] = f2tf32((tig & 1) ? v1 : v0);
            pa[kc][1] = f2tf32((tig & 1) ? v3 : v2);
            pa[kc][2] = f2tf32((tig & 1) ? w1 : w0);
            pa[kc][3] = f2tf32((tig & 1) ? w3 : w2);
        }

        // ---- O += P V ----
        #pragma unroll
        for (int kc = 0; kc < 8; kc++) {
            const int k0 = kc * 8;
            #pragma unroll
            for (int nt = 0; nt < 8; nt++) {
                const int n = nt * 8 + grp;
                const uint32_t b0 = f2tf32(vb_s[(k0 + tig) * VSTR + n]);
                const uint32_t b1 = f2tf32(vb_s[(k0 + tig + 4) * VSTR + n]);
                mma_tf32(o[nt], pa[kc], b0, b1);
            }
        }

        __syncthreads();  // all warps done with buf before it is restaged
    }

    // ---- epilogue ----
    const float inv0 = 1.0f / l0;
    const float inv1 = 1.0f / l1;
    const int gr0 = qbase + rl0;
    const int gr1 = qbase + rl1;
    #pragma unroll
    for (int nt = 0; nt < 8; nt++) {
        const int c = nt * 8 + 2 * tig;
        *(float2*)(O + (size_t)gr0 * HEAD + c) = make_float2(o[nt][0] * inv0, o[nt][1] * inv0);
        *(float2*)(O + (size_t)gr1 * HEAD + c) = make_float2(o[nt][2] * inv1, o[nt][3] * inv1);
    }
}

// ================= launch =================
extern "C" void kernel_launch(void* const* d_in, const int* in_sizes, int n_in,
                              void* d_out, int out_size)
{
    const float* x     = (const float*)d_in[0];
    const float* gamma = (const float*)d_in[1];
    const float* beta  = (const float*)d_in[2];
    const float* Wq    = (const float*)d_in[3];
    const float* Wk    = (const float*)d_in[4];
    const float* Wv    = (const float*)d_in[5];
    float* out = (float*)d_out;

    cudaFuncSetAttribute(ln_qkv_kernel,   cudaFuncAttributeMaxDynamicSharedMemorySize, (int)K1_SMEM);
    cudaFuncSetAttribute(attn_mma_kernel, cudaFuncAttributeMaxDynamicSharedMemorySize, (int)K2_SMEM);

    ln_qkv_kernel<<<NROWS / K1_TM, 256, K1_SMEM>>>(x, gamma, beta, Wq, Wk, Wv);
    attn_mma_kernel<<<BATCH * 32, 128, K2_SMEM>>>(out);
}

// round 5
// speedup vs baseline: 6.6971x; 1.3204x over previous
#include <cuda_runtime.h>
#include <cuda_bf16.h>
#include <stdint.h>
#include <math.h>

// Problem constants
#define BATCH 4
#define SEQ   2048
#define EMB   1024
#define HEAD  64
#define NROWS (BATCH * SEQ)   // 8192
#define SPLITK 2

// ---------------- scratch ----------------
__device__ float g_q[NROWS * HEAD];   // stored pre-rounded to tf32
__device__ float g_k[NROWS * HEAD];   // stored pre-rounded to tf32
__device__ float g_v[NROWS * HEAD];   // stored pre-rounded to tf32
__device__ float g_om[SPLITK * NROWS * HEAD];  // unnormalized partial O
__device__ float g_m [SPLITK * NROWS];
__device__ float g_l [SPLITK * NROWS];

__device__ __forceinline__ uint32_t f2tf32(float f) {
    uint32_t r;
    asm("cvt.rna.tf32.f32 %0, %1;" : "=r"(r) : "f"(f));
    return r;
}
__device__ __forceinline__ float tf32r(float f) { return __uint_as_float(f2tf32(f)); }

__device__ __forceinline__ void mma_tf32(float* d, const uint32_t* a,
                                         uint32_t b0, uint32_t b1) {
    asm volatile(
        "mma.sync.aligned.m16n8k8.row.col.f32.tf32.tf32.f32 "
        "{%0,%1,%2,%3}, {%4,%5,%6,%7}, {%8,%9}, {%0,%1,%2,%3};"
        : "+f"(d[0]), "+f"(d[1]), "+f"(d[2]), "+f"(d[3])
        : "r"(a[0]), "r"(a[1]), "r"(a[2]), "r"(a[3]), "r"(b0), "r"(b1));
}

__device__ __forceinline__ uint32_t smem_u32(const void* p) {
    return (uint32_t)__cvta_generic_to_shared(p);
}

#define CP_ASYNC16(dst_u32, src_ptr) \
    asm volatile("cp.async.cg.shared.global [%0], [%1], 16;" \
                 :: "r"(dst_u32), "l"(src_ptr))
#define CP_COMMIT() asm volatile("cp.async.commit_group;")
#define CP_WAIT(N)  asm volatile("cp.async.wait_group %0;" :: "n"(N))

// ================= Kernel 1: LayerNorm + QKV projection (tf32 tensor cores) ===
#define K1_TM 64
#define K1_KC 64
#define ASTR 68
#define BSTR 68
#define K1_SMEM ((K1_TM*ASTR + 192*BSTR + 128) * sizeof(float))

__global__ void __launch_bounds__(256, 2)
ln_qkv_kernel(const float* __restrict__ x,
              const float* __restrict__ gamma,
              const float* __restrict__ beta,
              const float* __restrict__ Wq,
              const float* __restrict__ Wk,
              const float* __restrict__ Wv)
{
    extern __shared__ float sm1[];
    float* A_s  = sm1;                       // [64][68]
    float* B_s  = sm1 + K1_TM * ASTR;        // [192][68]
    float* mu_s = B_s + 192 * BSTR;          // [64]
    float* rs_s = mu_s + 64;                 // [64]

    const int tid  = threadIdx.x;
    const int warp = tid >> 5;
    const int lane = tid & 31;
    const int rowBase = blockIdx.x * K1_TM;

    #pragma unroll
    for (int rr = 0; rr < 8; rr++) {
        const int r = warp * 8 + rr;
        const float4* xr = (const float4*)(x + (size_t)(rowBase + r) * EMB);
        float sum = 0.f, sq = 0.f;
        #pragma unroll
        for (int t = 0; t < 8; t++) {
            float4 v = xr[lane + 32 * t];
            sum += v.x + v.y + v.z + v.w;
            sq  += v.x*v.x + v.y*v.y + v.z*v.z + v.w*v.w;
        }
        #pragma unroll
        for (int off = 16; off; off >>= 1) {
            sum += __shfl_xor_sync(0xffffffffu, sum, off);
            sq  += __shfl_xor_sync(0xffffffffu, sq,  off);
        }
        if (lane == 0) {
            const float inv = 1.0f / (float)EMB;
            const float mu = sum * inv;
            const float var = sq * inv - mu * mu;
            mu_s[r] = mu;
            rs_s[r] = rsqrtf(var + 1e-5f);
        }
    }
    __syncthreads();

    const int wm  = warp >> 2;
    const int wn  = warp & 3;
    const int grp = lane >> 2;
    const int tig = lane & 3;

    float acc[12][4];
    #pragma unroll
    for (int i = 0; i < 12; i++)
        #pragma unroll
        for (int j = 0; j < 4; j++) acc[i][j] = 0.f;

    for (int ch = 0; ch < EMB / K1_KC; ch++) {
        const int k0 = ch * K1_KC;
        __syncthreads();

        #pragma unroll
        for (int j = 0; j < 4; j++) {
            const int idx = tid + 256 * j;
            const int row = idx >> 4;
            const int kg  = idx & 15;
            const float4 xv = *(const float4*)(x + (size_t)(rowBase + row) * EMB + k0 + kg * 4);
            const float4 gg = *(const float4*)(gamma + k0 + kg * 4);
            const float4 bb = *(const float4*)(beta  + k0 + kg * 4);
            const float mu = mu_s[row], rs = rs_s[row];
            float4 o;
            o.x = tf32r((xv.x - mu) * rs * gg.x + bb.x);
            o.y = tf32r((xv.y - mu) * rs * gg.y + bb.y);
            o.z = tf32r((xv.z - mu) * rs * gg.z + bb.z);
            o.w = tf32r((xv.w - mu) * rs * gg.w + bb.w);
            *(float4*)(A_s + row * ASTR + kg * 4) = o;
        }
        #pragma unroll
        for (int j = 0; j < 12; j++) {
            const int idx = tid + 256 * j;
            const int c   = idx >> 4;
            const int kg  = idx & 15;
            const float* Wr = (c < 64)  ? (Wq + (size_t)c * EMB)
                            : (c < 128) ? (Wk + (size_t)(c - 64) * EMB)
                                        : (Wv + (size_t)(c - 128) * EMB);
            const float4 wv = *(const float4*)(Wr + k0 + kg * 4);
            float4 o;
            o.x = tf32r(wv.x);
            o.y = tf32r(wv.y);
            o.z = tf32r(wv.z);
            o.w = tf32r(wv.w);
            *(float4*)(B_s + c * BSTR + kg * 4) = o;
        }
        __syncthreads();

        #pragma unroll
        for (int k8 = 0; k8 < 8; k8++) {
            const int kk = k8 * 8;
            uint32_t a[2][4];
            #pragma unroll
            for (int tm = 0; tm < 2; tm++) {
                const int rr = wm * 32 + tm * 16 + grp;
                a[tm][0] = __float_as_uint(A_s[rr * ASTR + kk + tig]);
                a[tm][1] = __float_as_uint(A_s[(rr + 8) * ASTR + kk + tig]);
                a[tm][2] = __float_as_uint(A_s[rr * ASTR + kk + tig + 4]);
                a[tm][3] = __float_as_uint(A_s[(rr + 8) * ASTR + kk + tig + 4]);
            }
            #pragma unroll
            for (int tn = 0; tn < 6; tn++) {
                const int bc = wn * 48 + tn * 8 + grp;
                const uint32_t b0 = __float_as_uint(B_s[bc * BSTR + kk + tig]);
                const uint32_t b1 = __float_as_uint(B_s[bc * BSTR + kk + tig + 4]);
                mma_tf32(acc[0 * 6 + tn], a[0], b0, b1);
                mma_tf32(acc[1 * 6 + tn], a[1], b0, b1);
            }
        }
    }

    // epilogue: round to tf32 so attention can skip all K/V/Q cvts
    #pragma unroll
    for (int tm = 0; tm < 2; tm++) {
        #pragma unroll
        for (int tn = 0; tn < 6; tn++) {
            const int i = tm * 6 + tn;
            const int r0 = rowBase + wm * 32 + tm * 16 + grp;
            const int c  = wn * 48 + tn * 8 + tig * 2;
            float* dst = (c < 64)  ? (g_q + (size_t)r0 * HEAD + c)
                       : (c < 128) ? (g_k + (size_t)r0 * HEAD + (c - 64))
                                   : (g_v + (size_t)r0 * HEAD + (c - 128));
            *(float2*)dst = make_float2(tf32r(acc[i][0]), tf32r(acc[i][1]));
            *(float2*)(dst + 8 * HEAD) = make_float2(tf32r(acc[i][2]), tf32r(acc[i][3]));
        }
    }
}

// ================= Kernel 2: causal flash attention (tf32 mma, split-KV x2) ===
// Grid = 4 batches x 32 q-tiles x 2 halves = 256 blocks, 128 threads.
// Half h processes KV tiles {h, h+2, ...} <= qt; partials combined by kernel 3.
#define QSTR 68
#define KSTR 68
#define VSTR 72
#define K2_SMEM ((64*QSTR + 2*64*KSTR + 2*64*VSTR) * sizeof(float))

__global__ void __launch_bounds__(128)
attn_mma_kernel()
{
    extern __shared__ float sm2[];
    float* q_s = sm2;                       // [64][68]
    float* k_s = q_s + 64 * QSTR;           // [2][64][68]
    float* v_s = k_s + 2 * 64 * KSTR;       // [2][64][72]

    const int tid  = threadIdx.x;
    const int warp = tid >> 5;
    const int lane = tid & 31;
    const int grp  = lane >> 2;
    const int tig  = lane & 3;

    const int b  = blockIdx.x >> 6;
    const int qt = (blockIdx.x >> 1) & 31;
    const int h  = blockIdx.x & 1;
    const int qbase = qt * 64;
    const int nkv = (qt >= h) ? (((qt - h) >> 1) + 1) : 0;

    float* OM = g_om + ((size_t)h * NROWS + (size_t)b * SEQ + qbase) * HEAD;
    float* M_ = g_m + (size_t)h * NROWS + (size_t)b * SEQ + qbase;
    float* L_ = g_l + (size_t)h * NROWS + (size_t)b * SEQ + qbase;

    if (nkv == 0) {  // empty half: neutral partials
        float4* om4 = (float4*)OM;
        for (int i = tid; i < 64 * 16; i += 128)
            om4[i] = make_float4(0.f, 0.f, 0.f, 0.f);
        if (tid < 64) { M_[tid] = -1e30f; L_[tid] = 0.f; }
        return;
    }

    const float* Q = g_q + (size_t)b * SEQ * HEAD + (size_t)qbase * HEAD;
    const float* K = g_k + (size_t)b * SEQ * HEAD;
    const float* V = g_v + (size_t)b * SEQ * HEAD;

    const uint32_t q_u = smem_u32(q_s);
    const uint32_t k_u = smem_u32(k_s);
    const uint32_t v_u = smem_u32(v_s);

    // stage Q + first KV tile (index h)
    {
        #pragma unroll
        for (int i = 0; i < 8; i++) {
            const int idx = tid + 128 * i;
            const int row = idx >> 4, c4 = idx & 15;
            CP_ASYNC16(q_u + (row * QSTR + c4 * 4) * 4, Q + row * HEAD + c4 * 4);
        }
        const float* Kg = K + (size_t)h * 64 * HEAD;
        const float* Vg = V + (size_t)h * 64 * HEAD;
        #pragma unroll
        for (int i = 0; i < 8; i++) {
            const int idx = tid + 128 * i;
            const int row = idx >> 4, c4 = idx & 15;
            CP_ASYNC16(k_u + (row * KSTR + c4 * 4) * 4, Kg + row * HEAD + c4 * 4);
            CP_ASYNC16(v_u + (row * VSTR + c4 * 4) * 4, Vg + row * HEAD + c4 * 4);
        }
        CP_COMMIT();
    }

    CP_WAIT(0);
    __syncthreads();

    // Q fragments: values are already tf32; *0.125f (2^-3) is exact
    uint32_t qa[8][4];
    {
        const int r0 = warp * 16 + grp;
        #pragma unroll
        for (int kc = 0; kc < 8; kc++) {
            const int kk = kc * 8;
            qa[kc][0] = __float_as_uint(0.125f * q_s[r0 * QSTR + kk + tig]);
            qa[kc][1] = __float_as_uint(0.125f * q_s[(r0 + 8) * QSTR + kk + tig]);
            qa[kc][2] = __float_as_uint(0.125f * q_s[r0 * QSTR + kk + tig + 4]);
            qa[kc][3] = __float_as_uint(0.125f * q_s[(r0 + 8) * QSTR + kk + tig + 4]);
        }
    }

    float o[8][4];
    #pragma unroll
    for (int nt = 0; nt < 8; nt++)
        #pragma unroll
        for (int j = 0; j < 4; j++) o[nt][j] = 0.f;
    float m0 = -1e30f, m1 = -1e30f, l0 = 0.f, l1 = 0.f;

    const int src_lo = (grp << 2) + (tig >> 1);
    const int src_hi = src_lo + 2;
    const int rl0 = warp * 16 + grp;
    const int rl1 = rl0 + 8;

    for (int i = 0; i < nkv; i++) {
        const int kt  = h + 2 * i;
        const int buf = i & 1;

        if (i + 1 < nkv) {
            const int nb = (i + 1) & 1;
            const float* Kg = K + (size_t)(kt + 2) * 64 * HEAD;
            const float* Vg = V + (size_t)(kt + 2) * 64 * HEAD;
            #pragma unroll
            for (int u = 0; u < 8; u++) {
                const int idx = tid + 128 * u;
                const int row = idx >> 4, c4 = idx & 15;
                CP_ASYNC16(k_u + (nb * 64 * KSTR + row * KSTR + c4 * 4) * 4,
                           Kg + row * HEAD + c4 * 4);
                CP_ASYNC16(v_u + (nb * 64 * VSTR + row * VSTR + c4 * 4) * 4,
                           Vg + row * HEAD + c4 * 4);
            }
            CP_COMMIT();
            CP_WAIT(1);
        } else {
            CP_WAIT(0);
        }
        __syncthreads();

        const float* kb_s = k_s + buf * 64 * KSTR;
        const float* vb_s = v_s + buf * 64 * VSTR;

        // S = Q K^T (K already tf32 in smem -> raw bit loads)
        float s[8][4];
        #pragma unroll
        for (int nt = 0; nt < 8; nt++)
            #pragma unroll
            for (int j = 0; j < 4; j++) s[nt][j] = 0.f;

        #pragma unroll
        for (int kc = 0; kc < 8; kc++) {
            const int kk = kc * 8;
            #pragma unroll
            for (int nt = 0; nt < 8; nt++) {
                const int n = nt * 8 + grp;
                const uint32_t b0 = __float_as_uint(kb_s[n * KSTR + kk + tig]);
                const uint32_t b1 = __float_as_uint(kb_s[n * KSTR + kk + tig + 4]);
                mma_tf32(s[nt], qa[kc], b0, b1);
            }
        }

        if (kt == qt) {
            #pragma unroll
            for (int nt = 0; nt < 8; nt++) {
                const int c0 = nt * 8 + 2 * tig;
                if (c0     > rl0) s[nt][0] = -1e30f;
                if (c0 + 1 > rl0) s[nt][1] = -1e30f;
                if (c0     > rl1) s[nt][2] = -1e30f;
                if (c0 + 1 > rl1) s[nt][3] = -1e30f;
            }
        }

        // online softmax (register/quad only)
        float mx0 = -1e30f, mx1 = -1e30f;
        #pragma unroll
        for (int nt = 0; nt < 8; nt++) {
            mx0 = fmaxf(mx0, fmaxf(s[nt][0], s[nt][1]));
            mx1 = fmaxf(mx1, fmaxf(s[nt][2], s[nt][3]));
        }
        mx0 = fmaxf(mx0, __shfl_xor_sync(0xffffffffu, mx0, 1));
        mx0 = fmaxf(mx0, __shfl_xor_sync(0xffffffffu, mx0, 2));
        mx1 = fmaxf(mx1, __shfl_xor_sync(0xffffffffu, mx1, 1));
        mx1 = fmaxf(mx1, __shfl_xor_sync(0xffffffffu, mx1, 2));

        const float mn0 = fmaxf(m0, mx0);
        const float mn1 = fmaxf(m1, mx1);
        const float cor0 = __expf(m0 - mn0);
        const float cor1 = __expf(m1 - mn1);
        m0 = mn0; m1 = mn1;

        float sum0 = 0.f, sum1 = 0.f;
        #pragma unroll
        for (int nt = 0; nt < 8; nt++) {
            s[nt][0] = __expf(s[nt][0] - mn0);
            s[nt][1] = __expf(s[nt][1] - mn0);
            s[nt][2] = __expf(s[nt][2] - mn1);
            s[nt][3] = __expf(s[nt][3] - mn1);
            sum0 += s[nt][0] + s[nt][1];
            sum1 += s[nt][2] + s[nt][3];
        }
        sum0 += __shfl_xor_sync(0xffffffffu, sum0, 1);
        sum0 += __shfl_xor_sync(0xffffffffu, sum0, 2);
        sum1 += __shfl_xor_sync(0xffffffffu, sum1, 1);
        sum1 += __shfl_xor_sync(0xffffffffu, sum1, 2);
        l0 = l0 * cor0 + sum0;
        l1 = l1 * cor1 + sum1;

        #pragma unroll
        for (int nt = 0; nt < 8; nt++) {
            o[nt][0] *= cor0; o[nt][1] *= cor0;
            o[nt][2] *= cor1; o[nt][3] *= cor1;
        }

        // P (C-frag) -> A-frag via quad shuffles (only remaining cvt)
        uint32_t pa[8][4];
        #pragma unroll
        for (int kc = 0; kc < 8; kc++) {
            const float v0 = __shfl_sync(0xffffffffu, s[kc][0], src_lo);
            const float v1 = __shfl_sync(0xffffffffu, s[kc][1], src_lo);
            const float v2 = __shfl_sync(0xffffffffu, s[kc][2], src_lo);
            const float v3 = __shfl_sync(0xffffffffu, s[kc][3], src_lo);
            const float w0 = __shfl_sync(0xffffffffu, s[kc][0], src_hi);
            const float w1 = __shfl_sync(0xffffffffu, s[kc][1], src_hi);
            const float w2 = __shfl_sync(0xffffffffu, s[kc][2], src_hi);
            const float w3 = __shfl_sync(0xffffffffu, s[kc][3], src_hi);
            pa[kc][0] = f2tf32((tig & 1) ? v1 : v0);
            pa[kc][1] = f2tf32((tig & 1) ? v3 : v2);
            pa[kc][2] = f2tf32((tig & 1) ? w1 : w0);
            pa[kc][3] = f2tf32((tig & 1) ? w3 : w2);
        }

        // O += P V (V already tf32 in smem)
        #pragma unroll
        for (int kc = 0; kc < 8; kc++) {
            const int k0 = kc * 8;
            #pragma unroll
            for (int nt = 0; nt < 8; nt++) {
                const int n = nt * 8 + grp;
                const uint32_t b0 = __float_as_uint(vb_s[(k0 + tig) * VSTR + n]);
                const uint32_t b1 = __float_as_uint(vb_s[(k0 + tig + 4) * VSTR + n]);
                mma_tf32(o[nt], pa[kc], b0, b1);
            }
        }

        __syncthreads();
    }

    // epilogue: unnormalized partials + stats
    #pragma unroll
    for (int nt = 0; nt < 8; nt++) {
        const int c = nt * 8 + 2 * tig;
        *(float2*)(OM + (size_t)rl0 * HEAD + c) = make_float2(o[nt][0], o[nt][1]);
        *(float2*)(OM + (size_t)rl1 * HEAD + c) = make_float2(o[nt][2], o[nt][3]);
    }
    if (tig == 0) {
        M_[rl0] = m0; L_[rl0] = l0;
        M_[rl1] = m1; L_[rl1] = l1;
    }
}

// ================= Kernel 3: split-KV combine =================
__global__ void __launch_bounds__(256)
combine_kernel(float* __restrict__ out)
{
    const int idx = blockIdx.x * 256 + threadIdx.x;  // row*16 + c4
    const int row = idx >> 4;
    const int c4  = idx & 15;

    const float m1 = g_m[row], m2 = g_m[NROWS + row];
    const float l1 = g_l[row], l2 = g_l[NROWS + row];
    const float M  = fmaxf(m1, m2);
    const float e1 = __expf(m1 - M);
    const float e2 = __expf(m2 - M);
    const float inv = 1.0f / (l1 * e1 + l2 * e2);
    const float a1 = e1 * inv, a2 = e2 * inv;

    const float4 o1 = *(const float4*)(g_om + (size_t)row * HEAD + c4 * 4);
    const float4 o2 = *(const float4*)(g_om + (size_t)(NROWS + row) * HEAD + c4 * 4);
    float4 r;
    r.x = o1.x * a1 + o2.x * a2;
    r.y = o1.y * a1 + o2.y * a2;
    r.z = o1.z * a1 + o2.z * a2;
    r.w = o1.w * a1 + o2.w * a2;
    *(float4*)(out + (size_t)row * HEAD + c4 * 4) = r;
}

// ================= launch =================
extern "C" void kernel_launch(void* const* d_in, const int* in_sizes, int n_in,
                              void* d_out, int out_size)
{
    const float* x     = (const float*)d_in[0];
    const float* gamma = (const float*)d_in[1];
    const float* beta  = (const float*)d_in[2];
    const float* Wq    = (const float*)d_in[3];
    const float* Wk    = (const float*)d_in[4];
    const float* Wv    = (const float*)d_in[5];
    float* out = (float*)d_out;

    cudaFuncSetAttribute(ln_qkv_kernel,   cudaFuncAttributeMaxDynamicSharedMemorySize, (int)K1_SMEM);
    cudaFuncSetAttribute(attn_mma_kernel, cudaFuncAttributeMaxDynamicSharedMemorySize, (int)K2_SMEM);

    ln_qkv_kernel<<<NROWS / K1_TM, 256, K1_SMEM>>>(x, gamma, beta, Wq, Wk, Wv);
    attn_mma_kernel<<<BATCH * 32 * SPLITK, 128, K2_SMEM>>>();
    combine_kernel<<<NROWS * 16 / 256, 256>>>(out);
}

// round 6
// speedup vs baseline: 6.9035x; 1.0308x over previous
#include <cuda_runtime.h>
#include <cuda_bf16.h>
#include <stdint.h>
#include <math.h>

// Problem constants
#define BATCH 4
#define SEQ   2048
#define EMB   1024
#define HEAD  64
#define NROWS (BATCH * SEQ)   // 8192
#define SPLITK 2

// ---------------- scratch ----------------
__device__ float g_q[NROWS * HEAD];   // tf32-rounded
__device__ float g_k[NROWS * HEAD];   // tf32-rounded
__device__ float g_v[NROWS * HEAD];   // tf32-rounded
__device__ float g_om[SPLITK * NROWS * HEAD];
__device__ float g_m [SPLITK * NROWS];
__device__ float g_l [SPLITK * NROWS];
__device__ float g_mu[NROWS];
__device__ float g_rs[NROWS];
__device__ float g_w [192 * EMB];     // gamma-folded, tf32-rounded weights (q|k|v)
__device__ float g_wsum [192];        // sum_e W'[c,e]
__device__ float g_wbeta[192];        // sum_e W[c,e]*beta[e]

__device__ __forceinline__ uint32_t f2tf32(float f) {
    uint32_t r;
    asm("cvt.rna.tf32.f32 %0, %1;" : "=r"(r) : "f"(f));
    return r;
}
__device__ __forceinline__ float tf32r(float f) { return __uint_as_float(f2tf32(f)); }

__device__ __forceinline__ void mma_tf32(float* d, const uint32_t* a,
                                         uint32_t b0, uint32_t b1) {
    asm volatile(
        "mma.sync.aligned.m16n8k8.row.col.f32.tf32.tf32.f32 "
        "{%0,%1,%2,%3}, {%4,%5,%6,%7}, {%8,%9}, {%0,%1,%2,%3};"
        : "+f"(d[0]), "+f"(d[1]), "+f"(d[2]), "+f"(d[3])
        : "r"(a[0]), "r"(a[1]), "r"(a[2]), "r"(a[3]), "r"(b0), "r"(b1));
}

__device__ __forceinline__ uint32_t smem_u32(const void* p) {
    return (uint32_t)__cvta_generic_to_shared(p);
}

#define CP_ASYNC16(dst_u32, src_ptr) \
    asm volatile("cp.async.cg.shared.global [%0], [%1], 16;" \
                 :: "r"(dst_u32), "l"(src_ptr))
#define CP_COMMIT() asm volatile("cp.async.commit_group;")
#define CP_WAIT(N)  asm volatile("cp.async.wait_group %0;" :: "n"(N))

// ================= Kernel 0a: LayerNorm stats =================
__global__ void __launch_bounds__(256)
ln_stats_kernel(const float* __restrict__ x)
{
    const int warp = threadIdx.x >> 5;
    const int lane = threadIdx.x & 31;
    const int r = blockIdx.x * 8 + warp;
    const float4* xr = (const float4*)(x + (size_t)r * EMB);
    float sum = 0.f, sq = 0.f;
    #pragma unroll
    for (int t = 0; t < 8; t++) {
        float4 v = xr[lane + 32 * t];
        sum += v.x + v.y + v.z + v.w;
        sq  += v.x*v.x + v.y*v.y + v.z*v.z + v.w*v.w;
    }
    #pragma unroll
    for (int off = 16; off; off >>= 1) {
        sum += __shfl_xor_sync(0xffffffffu, sum, off);
        sq  += __shfl_xor_sync(0xffffffffu, sq,  off);
    }
    if (lane == 0) {
        const float inv = 1.0f / (float)EMB;
        const float mu = sum * inv;
        const float var = sq * inv - mu * mu;
        g_mu[r] = mu;
        g_rs[r] = rsqrtf(var + 1e-5f);
    }
}

// ================= Kernel 0b: weight prep (fold gamma, round tf32) ===========
// One block per output column c (0..191). W' = W*gamma; wsum=sum W'; wbeta=sum W*beta.
__global__ void __launch_bounds__(256)
wprep_kernel(const float* __restrict__ gamma,
             const float* __restrict__ beta,
             const float* __restrict__ Wq,
             const float* __restrict__ Wk,
             const float* __restrict__ Wv)
{
    __shared__ float red[16];
    const int c   = blockIdx.x;
    const int tid = threadIdx.x;
    const int warp = tid >> 5, lane = tid & 31;
    const float* Wr = (c < 64)  ? (Wq + (size_t)c * EMB)
                    : (c < 128) ? (Wk + (size_t)(c - 64) * EMB)
                                : (Wv + (size_t)(c - 128) * EMB);
    float s_w = 0.f, s_b = 0.f;
    #pragma unroll
    for (int t = 0; t < 1; t++) {
        const int i4 = tid;  // 256 threads * 4 = 1024
        float4 w = *(const float4*)(Wr + i4 * 4);
        float4 g = *(const float4*)(gamma + i4 * 4);
        float4 b = *(const float4*)(beta  + i4 * 4);
        float4 o;
        o.x = tf32r(w.x * g.x); o.y = tf32r(w.y * g.y);
        o.z = tf32r(w.z * g.z); o.w = tf32r(w.w * g.w);
        *(float4*)(g_w + (size_t)c * EMB + i4 * 4) = o;
        s_w += o.x + o.y + o.z + o.w;
        s_b += w.x*b.x + w.y*b.y + w.z*b.z + w.w*b.w;
    }
    #pragma unroll
    for (int off = 16; off; off >>= 1) {
        s_w += __shfl_xor_sync(0xffffffffu, s_w, off);
        s_b += __shfl_xor_sync(0xffffffffu, s_b, off);
    }
    if (lane == 0) { red[warp] = s_w; red[warp + 8] = s_b; }
    __syncthreads();
    if (tid == 0) {
        float aw = 0.f, ab = 0.f;
        #pragma unroll
        for (int i = 0; i < 8; i++) { aw += red[i]; ab += red[i + 8]; }
        g_wsum[c] = aw; g_wbeta[c] = ab;
    }
}

// ================= Kernel 1: QKV GEMM (async, LN in epilogue) =================
// Block: M=64 x N=192, K=1024 in chunks of 64, double-buffered cp.async.
#define K1_KC 64
#define ASTR 68
#define BSTR 68
#define K1_SMEM ((2*64*ASTR + 2*192*BSTR) * sizeof(float))

__global__ void __launch_bounds__(256)
qkv_gemm_kernel(const float* __restrict__ x)
{
    extern __shared__ float sm1[];
    float* A_s = sm1;                    // [2][64][68]  raw x
    float* B_s = sm1 + 2 * 64 * ASTR;    // [2][192][68] tf32 W'

    const int tid  = threadIdx.x;
    const int warp = tid >> 5;
    const int lane = tid & 31;
    const int rowBase = blockIdx.x * 64;

    const uint32_t a_u = smem_u32(A_s);
    const uint32_t b_u = smem_u32(B_s);

    const int wm  = warp >> 2;
    const int wn  = warp & 3;
    const int grp = lane >> 2;
    const int tig = lane & 3;

    // stage chunk 0 into buffer 0
    {
        #pragma unroll
        for (int i = 0; i < 4; i++) {
            const int idx = tid + 256 * i;
            const int row = idx >> 4, c4 = idx & 15;
            CP_ASYNC16(a_u + (row * ASTR + c4 * 4) * 4,
                       x + (size_t)(rowBase + row) * EMB + c4 * 4);
        }
        #pragma unroll
        for (int i = 0; i < 12; i++) {
            const int idx = tid + 256 * i;
            const int c = idx >> 4, c4 = idx & 15;
            CP_ASYNC16(b_u + (c * BSTR + c4 * 4) * 4,
                       g_w + (size_t)c * EMB + c4 * 4);
        }
        CP_COMMIT();
    }

    float acc[12][4];
    #pragma unroll
    for (int i = 0; i < 12; i++)
        #pragma unroll
        for (int j = 0; j < 4; j++) acc[i][j] = 0.f;

    for (int ch = 0; ch < EMB / K1_KC; ch++) {
        const int buf = ch & 1;

        if (ch + 1 < EMB / K1_KC) {
            const int nb = (ch + 1) & 1;
            const int k0 = (ch + 1) * K1_KC;
            #pragma unroll
            for (int i = 0; i < 4; i++) {
                const int idx = tid + 256 * i;
                const int row = idx >> 4, c4 = idx & 15;
                CP_ASYNC16(a_u + (nb * 64 * ASTR + row * ASTR + c4 * 4) * 4,
                           x + (size_t)(rowBase + row) * EMB + k0 + c4 * 4);
            }
            #pragma unroll
            for (int i = 0; i < 12; i++) {
                const int idx = tid + 256 * i;
                const int c = idx >> 4, c4 = idx & 15;
                CP_ASYNC16(b_u + (nb * 192 * BSTR + c * BSTR + c4 * 4) * 4,
                           g_w + (size_t)c * EMB + k0 + c4 * 4);
            }
            CP_COMMIT();
            CP_WAIT(1);
        } else {
            CP_WAIT(0);
        }
        __syncthreads();

        const float* Ab = A_s + buf * 64 * ASTR;
        const float* Bb = B_s + buf * 192 * BSTR;

        #pragma unroll
        for (int k8 = 0; k8 < 8; k8++) {
            const int kk = k8 * 8;
            uint32_t a[2][4];
            #pragma unroll
            for (int tm = 0; tm < 2; tm++) {
                const int rr = wm * 32 + tm * 16 + grp;
                a[tm][0] = f2tf32(Ab[rr * ASTR + kk + tig]);
                a[tm][1] = f2tf32(Ab[(rr + 8) * ASTR + kk + tig]);
                a[tm][2] = f2tf32(Ab[rr * ASTR + kk + tig + 4]);
                a[tm][3] = f2tf32(Ab[(rr + 8) * ASTR + kk + tig + 4]);
            }
            #pragma unroll
            for (int tn = 0; tn < 6; tn++) {
                const int bc = wn * 48 + tn * 8 + grp;
                const uint32_t b0 = __float_as_uint(Bb[bc * BSTR + kk + tig]);
                const uint32_t b1 = __float_as_uint(Bb[bc * BSTR + kk + tig + 4]);
                mma_tf32(acc[0 * 6 + tn], a[0], b0, b1);
                mma_tf32(acc[1 * 6 + tn], a[1], b0, b1);
            }
        }
        __syncthreads();
    }

    // epilogue: out = rs*(acc - mu*wsum) + wbeta, tf32-round, scatter
    #pragma unroll
    for (int tm = 0; tm < 2; tm++) {
        const int r0 = rowBase + wm * 32 + tm * 16 + grp;
        const float mu0 = g_mu[r0],     rs0 = g_rs[r0];
        const float mu1 = g_mu[r0 + 8], rs1 = g_rs[r0 + 8];
        #pragma unroll
        for (int tn = 0; tn < 6; tn++) {
            const int i = tm * 6 + tn;
            const int c = wn * 48 + tn * 8 + tig * 2;
            const float ws0 = g_wsum[c],  wb0 = g_wbeta[c];
            const float ws1 = g_wsum[c+1], wb1 = g_wbeta[c+1];
            float* dst = (c < 64)  ? (g_q + (size_t)r0 * HEAD + c)
                       : (c < 128) ? (g_k + (size_t)r0 * HEAD + (c - 64))
                                   : (g_v + (size_t)r0 * HEAD + (c - 128));
            *(float2*)dst = make_float2(
                tf32r(rs0 * (acc[i][0] - mu0 * ws0) + wb0),
                tf32r(rs0 * (acc[i][1] - mu0 * ws1) + wb1));
            *(float2*)(dst + 8 * HEAD) = make_float2(
                tf32r(rs1 * (acc[i][2] - mu1 * ws0) + wb0),
                tf32r(rs1 * (acc[i][3] - mu1 * ws1) + wb1));
        }
    }
}

// ================= Kernel 2: causal flash attention (tf32 mma, split-KV x2) ===
#define QSTR 68
#define KSTR 68
#define VSTR 72
#define K2_SMEM ((64*QSTR + 2*64*KSTR + 2*64*VSTR) * sizeof(float))

__global__ void __launch_bounds__(128)
attn_mma_kernel()
{
    extern __shared__ float sm2[];
    float* q_s = sm2;
    float* k_s = q_s + 64 * QSTR;
    float* v_s = k_s + 2 * 64 * KSTR;

    const int tid  = threadIdx.x;
    const int warp = tid >> 5;
    const int lane = tid & 31;
    const int grp  = lane >> 2;
    const int tig  = lane & 3;

    const int b  = blockIdx.x >> 6;
    const int qt = (blockIdx.x >> 1) & 31;
    const int h  = blockIdx.x & 1;
    const int qbase = qt * 64;
    const int nkv = (qt >= h) ? (((qt - h) >> 1) + 1) : 0;

    float* OM = g_om + ((size_t)h * NROWS + (size_t)b * SEQ + qbase) * HEAD;
    float* M_ = g_m + (size_t)h * NROWS + (size_t)b * SEQ + qbase;
    float* L_ = g_l + (size_t)h * NROWS + (size_t)b * SEQ + qbase;

    if (nkv == 0) {
        float4* om4 = (float4*)OM;
        for (int i = tid; i < 64 * 16; i += 128)
            om4[i] = make_float4(0.f, 0.f, 0.f, 0.f);
        if (tid < 64) { M_[tid] = -1e30f; L_[tid] = 0.f; }
        return;
    }

    const float* Q = g_q + (size_t)b * SEQ * HEAD + (size_t)qbase * HEAD;
    const float* K = g_k + (size_t)b * SEQ * HEAD;
    const float* V = g_v + (size_t)b * SEQ * HEAD;

    const uint32_t q_u = smem_u32(q_s);
    const uint32_t k_u = smem_u32(k_s);
    const uint32_t v_u = smem_u32(v_s);

    {
        #pragma unroll
        for (int i = 0; i < 8; i++) {
            const int idx = tid + 128 * i;
            const int row = idx >> 4, c4 = idx & 15;
            CP_ASYNC16(q_u + (row * QSTR + c4 * 4) * 4, Q + row * HEAD + c4 * 4);
        }
        const float* Kg = K + (size_t)h * 64 * HEAD;
        const float* Vg = V + (size_t)h * 64 * HEAD;
        #pragma unroll
        for (int i = 0; i < 8; i++) {
            const int idx = tid + 128 * i;
            const int row = idx >> 4, c4 = idx & 15;
            CP_ASYNC16(k_u + (row * KSTR + c4 * 4) * 4, Kg + row * HEAD + c4 * 4);
            CP_ASYNC16(v_u + (row * VSTR + c4 * 4) * 4, Vg + row * HEAD + c4 * 4);
        }
        CP_COMMIT();
    }

    CP_WAIT(0);
    __syncthreads();

    uint32_t qa[8][4];
    {
        const int r0 = warp * 16 + grp;
        #pragma unroll
        for (int kc = 0; kc < 8; kc++) {
            const int kk = kc * 8;
            qa[kc][0] = __float_as_uint(0.125f * q_s[r0 * QSTR + kk + tig]);
            qa[kc][1] = __float_as_uint(0.125f * q_s[(r0 + 8) * QSTR + kk + tig]);
            qa[kc][2] = __float_as_uint(0.125f * q_s[r0 * QSTR + kk + tig + 4]);
            qa[kc][3] = __float_as_uint(0.125f * q_s[(r0 + 8) * QSTR + kk + tig + 4]);
        }
    }

    float o[8][4];
    #pragma unroll
    for (int nt = 0; nt < 8; nt++)
        #pragma unroll
        for (int j = 0; j < 4; j++) o[nt][j] = 0.f;
    float m0 = -1e30f, m1 = -1e30f, l0 = 0.f, l1 = 0.f;

    const int src_lo = (grp << 2) + (tig >> 1);
    const int src_hi = src_lo + 2;
    const int rl0 = warp * 16 + grp;
    const int rl1 = rl0 + 8;

    for (int i = 0; i < nkv; i++) {
        const int kt  = h + 2 * i;
        const int buf = i & 1;

        if (i + 1 < nkv) {
            const int nb = (i + 1) & 1;
            const float* Kg = K + (size_t)(kt + 2) * 64 * HEAD;
            const float* Vg = V + (size_t)(kt + 2) * 64 * HEAD;
            #pragma unroll
            for (int u = 0; u < 8; u++) {
                const int idx = tid + 128 * u;
                const int row = idx >> 4, c4 = idx & 15;
                CP_ASYNC16(k_u + (nb * 64 * KSTR + row * KSTR + c4 * 4) * 4,
                           Kg + row * HEAD + c4 * 4);
                CP_ASYNC16(v_u + (nb * 64 * VSTR + row * VSTR + c4 * 4) * 4,
                           Vg + row * HEAD + c4 * 4);
            }
            CP_COMMIT();
            CP_WAIT(1);
        } else {
            CP_WAIT(0);
        }
        __syncthreads();

        const float* kb_s = k_s + buf * 64 * KSTR;
        const float* vb_s = v_s + buf * 64 * VSTR;

        float s[8][4];
        #pragma unroll
        for (int nt = 0; nt < 8; nt++)
            #pragma unroll
            for (int j = 0; j < 4; j++) s[nt][j] = 0.f;

        #pragma unroll
        for (int kc = 0; kc < 8; kc++) {
            const int kk = kc * 8;
            #pragma unroll
            for (int nt = 0; nt < 8; nt++) {
                const int n = nt * 8 + grp;
                const uint32_t b0 = __float_as_uint(kb_s[n * KSTR + kk + tig]);
                const uint32_t b1 = __float_as_uint(kb_s[n * KSTR + kk + tig + 4]);
                mma_tf32(s[nt], qa[kc], b0, b1);
            }
        }

        if (kt == qt) {
            #pragma unroll
            for (int nt = 0; nt < 8; nt++) {
                const int c0 = nt * 8 + 2 * tig;
                if (c0     > rl0) s[nt][0] = -1e30f;
                if (c0 + 1 > rl0) s[nt][1] = -1e30f;
                if (c0     > rl1) s[nt][2] = -1e30f;
                if (c0 + 1 > rl1) s[nt][3] = -1e30f;
            }
        }

        float mx0 = -1e30f, mx1 = -1e30f;
        #pragma unroll
        for (int nt = 0; nt < 8; nt++) {
            mx0 = fmaxf(mx0, fmaxf(s[nt][0], s[nt][1]));
            mx1 = fmaxf(mx1, fmaxf(s[nt][2], s[nt][3]));
        }
        mx0 = fmaxf(mx0, __shfl_xor_sync(0xffffffffu, mx0, 1));
        mx0 = fmaxf(mx0, __shfl_xor_sync(0xffffffffu, mx0, 2));
        mx1 = fmaxf(mx1, __shfl_xor_sync(0xffffffffu, mx1, 1));
        mx1 = fmaxf(mx1, __shfl_xor_sync(0xffffffffu, mx1, 2));

        const float mn0 = fmaxf(m0, mx0);
        const float mn1 = fmaxf(m1, mx1);
        const float cor0 = __expf(m0 - mn0);
        const float cor1 = __expf(m1 - mn1);
        m0 = mn0; m1 = mn1;

        float sum0 = 0.f, sum1 = 0.f;
        #pragma unroll
        for (int nt = 0; nt < 8; nt++) {
            s[nt][0] = __expf(s[nt][0] - mn0);
            s[nt][1] = __expf(s[nt][1] - mn0);
            s[nt][2] = __expf(s[nt][2] - mn1);
            s[nt][3] = __expf(s[nt][3] - mn1);
            sum0 += s[nt][0] + s[nt][1];
            sum1 += s[nt][2] + s[nt][3];
        }
        sum0 += __shfl_xor_sync(0xffffffffu, sum0, 1);
        sum0 += __shfl_xor_sync(0xffffffffu, sum0, 2);
        sum1 += __shfl_xor_sync(0xffffffffu, sum1, 1);
        sum1 += __shfl_xor_sync(0xffffffffu, sum1, 2);
        l0 = l0 * cor0 + sum0;
        l1 = l1 * cor1 + sum1;

        #pragma unroll
        for (int nt = 0; nt < 8; nt++) {
            o[nt][0] *= cor0; o[nt][1] *= cor0;
            o[nt][2] *= cor1; o[nt][3] *= cor1;
        }

        uint32_t pa[8][4];
        #pragma unroll
        for (int kc = 0; kc < 8; kc++) {
            const float v0 = __shfl_sync(0xffffffffu, s[kc][0], src_lo);
            const float v1 = __shfl_sync(0xffffffffu, s[kc][1], src_lo);
            const float v2 = __shfl_sync(0xffffffffu, s[kc][2], src_lo);
            const float v3 = __shfl_sync(0xffffffffu, s[kc][3], src_lo);
            const float w0 = __shfl_sync(0xffffffffu, s[kc][0], src_hi);
            const float w1 = __shfl_sync(0xffffffffu, s[kc][1], src_hi);
            const float w2 = __shfl_sync(0xffffffffu, s[kc][2], src_hi);
            const float w3 = __shfl_sync(0xffffffffu, s[kc][3], src_hi);
            pa[kc][0] = f2tf32((tig & 1) ? v1 : v0);
            pa[kc][1] = f2tf32((tig & 1) ? v3 : v2);
            pa[kc][2] = f2tf32((tig & 1) ? w1 : w0);
            pa[kc][3] = f2tf32((tig & 1) ? w3 : w2);
        }

        #pragma unroll
        for (int kc = 0; kc < 8; kc++) {
            const int k0 = kc * 8;
            #pragma unroll
            for (int nt = 0; nt < 8; nt++) {
                const int n = nt * 8 + grp;
                const uint32_t b0 = __float_as_uint(vb_s[(k0 + tig) * VSTR + n]);
                const uint32_t b1 = __float_as_uint(vb_s[(k0 + tig + 4) * VSTR + n]);
                mma_tf32(o[nt], pa[kc], b0, b1);
            }
        }

        __syncthreads();
    }

    #pragma unroll
    for (int nt = 0; nt < 8; nt++) {
        const int c = nt * 8 + 2 * tig;
        *(float2*)(OM + (size_t)rl0 * HEAD + c) = make_float2(o[nt][0], o[nt][1]);
        *(float2*)(OM + (size_t)rl1 * HEAD + c) = make_float2(o[nt][2], o[nt][3]);
    }
    if (tig == 0) {
        M_[rl0] = m0; L_[rl0] = l0;
        M_[rl1] = m1; L_[rl1] = l1;
    }
}

// ================= Kernel 3: split-KV combine =================
__global__ void __launch_bounds__(256)
combine_kernel(float* __restrict__ out)
{
    const int idx = blockIdx.x * 256 + threadIdx.x;
    const int row = idx >> 4;
    const int c4  = idx & 15;

    const float m1 = g_m[row], m2 = g_m[NROWS + row];
    const float l1 = g_l[row], l2 = g_l[NROWS + row];
    const float M  = fmaxf(m1, m2);
    const float e1 = __expf(m1 - M);
    const float e2 = __expf(m2 - M);
    const float inv = 1.0f / (l1 * e1 + l2 * e2);
    const float a1 = e1 * inv, a2 = e2 * inv;

    const float4 o1 = *(const float4*)(g_om + (size_t)row * HEAD + c4 * 4);
    const float4 o2 = *(const float4*)(g_om + (size_t)(NROWS + row) * HEAD + c4 * 4);
    float4 r;
    r.x = o1.x * a1 + o2.x * a2;
    r.y = o1.y * a1 + o2.y * a2;
    r.z = o1.z * a1 + o2.z * a2;
    r.w = o1.w * a1 + o2.w * a2;
    *(float4*)(out + (size_t)row * HEAD + c4 * 4) = r;
}

// ================= launch =================
extern "C" void kernel_launch(void* const* d_in, const int* in_sizes, int n_in,
                              void* d_out, int out_size)
{
    const float* x     = (const float*)d_in[0];
    const float* gamma = (const float*)d_in[1];
    const float* beta  = (const float*)d_in[2];
    const float* Wq    = (const float*)d_in[3];
    const float* Wk    = (const float*)d_in[4];
    const float* Wv    = (const float*)d_in[5];
    float* out = (float*)d_out;

    cudaFuncSetAttribute(qkv_gemm_kernel, cudaFuncAttributeMaxDynamicSharedMemorySize, (int)K1_SMEM);
    cudaFuncSetAttribute(attn_mma_kernel, cudaFuncAttributeMaxDynamicSharedMemorySize, (int)K2_SMEM);

    ln_stats_kernel<<<NROWS / 8, 256>>>(x);
    wprep_kernel<<<192, 256>>>(gamma, beta, Wq, Wk, Wv);
    qkv_gemm_kernel<<<NROWS / 64, 256, K1_SMEM>>>(x);
    attn_mma_kernel<<<BATCH * 32 * SPLITK, 128, K2_SMEM>>>();
    combine_kernel<<<NROWS * 16 / 256, 256>>>(out);
}

// round 7
// speedup vs baseline: 7.6952x; 1.1147x over previous
#include <cuda_runtime.h>
#include <cuda_bf16.h>
#include <stdint.h>
#include <math.h>

// Problem constants
#define BATCH 4
#define SEQ   2048
#define EMB   1024
#define HEAD  64
#define NROWS (BATCH * SEQ)   // 8192
#define SPLITK 4

// ---------------- scratch ----------------
__device__ float g_q[NROWS * HEAD];   // tf32-rounded
__device__ float g_k[NROWS * HEAD];   // tf32-rounded
__device__ float g_v[NROWS * HEAD];   // tf32-rounded
__device__ float g_om[SPLITK * NROWS * HEAD];
__device__ float g_m [SPLITK * NROWS];
__device__ float g_l [SPLITK * NROWS];
__device__ float g_mu[NROWS];
__device__ float g_rs[NROWS];
__device__ float g_w [192 * EMB];     // gamma-folded, tf32-rounded weights (q|k|v)
__device__ float g_wsum [192];
__device__ float g_wbeta[192];

__device__ __forceinline__ uint32_t f2tf32(float f) {
    uint32_t r;
    asm("cvt.rna.tf32.f32 %0, %1;" : "=r"(r) : "f"(f));
    return r;
}
__device__ __forceinline__ float tf32r(float f) { return __uint_as_float(f2tf32(f)); }

__device__ __forceinline__ void mma_tf32(float* d, const uint32_t* a,
                                         uint32_t b0, uint32_t b1) {
    asm volatile(
        "mma.sync.aligned.m16n8k8.row.col.f32.tf32.tf32.f32 "
        "{%0,%1,%2,%3}, {%4,%5,%6,%7}, {%8,%9}, {%0,%1,%2,%3};"
        : "+f"(d[0]), "+f"(d[1]), "+f"(d[2]), "+f"(d[3])
        : "r"(a[0]), "r"(a[1]), "r"(a[2]), "r"(a[3]), "r"(b0), "r"(b1));
}

__device__ __forceinline__ uint32_t smem_u32(const void* p) {
    return (uint32_t)__cvta_generic_to_shared(p);
}

#define CP_ASYNC16(dst_u32, src_ptr) \
    asm volatile("cp.async.cg.shared.global [%0], [%1], 16;" \
                 :: "r"(dst_u32), "l"(src_ptr))
#define CP_COMMIT() asm volatile("cp.async.commit_group;")
#define CP_WAIT(N)  asm volatile("cp.async.wait_group %0;" :: "n"(N))

// ================= Kernel 0a: LayerNorm stats =================
__global__ void __launch_bounds__(256)
ln_stats_kernel(const float* __restrict__ x)
{
    const int warp = threadIdx.x >> 5;
    const int lane = threadIdx.x & 31;
    const int r = blockIdx.x * 8 + warp;
    const float4* xr = (const float4*)(x + (size_t)r * EMB);
    float sum = 0.f, sq = 0.f;
    #pragma unroll
    for (int t = 0; t < 8; t++) {
        float4 v = xr[lane + 32 * t];
        sum += v.x + v.y + v.z + v.w;
        sq  += v.x*v.x + v.y*v.y + v.z*v.z + v.w*v.w;
    }
    #pragma unroll
    for (int off = 16; off; off >>= 1) {
        sum += __shfl_xor_sync(0xffffffffu, sum, off);
        sq  += __shfl_xor_sync(0xffffffffu, sq,  off);
    }
    if (lane == 0) {
        const float inv = 1.0f / (float)EMB;
        const float mu = sum * inv;
        const float var = sq * inv - mu * mu;
        g_mu[r] = mu;
        g_rs[r] = rsqrtf(var + 1e-5f);
    }
}

// ================= Kernel 0b: weight prep =================
__global__ void __launch_bounds__(256)
wprep_kernel(const float* __restrict__ gamma,
             const float* __restrict__ beta,
             const float* __restrict__ Wq,
             const float* __restrict__ Wk,
             const float* __restrict__ Wv)
{
    __shared__ float red[16];
    const int c   = blockIdx.x;
    const int tid = threadIdx.x;
    const int warp = tid >> 5, lane = tid & 31;
    const float* Wr = (c < 64)  ? (Wq + (size_t)c * EMB)
                    : (c < 128) ? (Wk + (size_t)(c - 64) * EMB)
                                : (Wv + (size_t)(c - 128) * EMB);
    float s_w = 0.f, s_b = 0.f;
    {
        const int i4 = tid;
        float4 w = *(const float4*)(Wr + i4 * 4);
        float4 g = *(const float4*)(gamma + i4 * 4);
        float4 b = *(const float4*)(beta  + i4 * 4);
        float4 o;
        o.x = tf32r(w.x * g.x); o.y = tf32r(w.y * g.y);
        o.z = tf32r(w.z * g.z); o.w = tf32r(w.w * g.w);
        *(float4*)(g_w + (size_t)c * EMB + i4 * 4) = o;
        s_w += o.x + o.y + o.z + o.w;
        s_b += w.x*b.x + w.y*b.y + w.z*b.z + w.w*b.w;
    }
    #pragma unroll
    for (int off = 16; off; off >>= 1) {
        s_w += __shfl_xor_sync(0xffffffffu, s_w, off);
        s_b += __shfl_xor_sync(0xffffffffu, s_b, off);
    }
    if (lane == 0) { red[warp] = s_w; red[warp + 8] = s_b; }
    __syncthreads();
    if (tid == 0) {
        float aw = 0.f, ab = 0.f;
        #pragma unroll
        for (int i = 0; i < 8; i++) { aw += red[i]; ab += red[i + 8]; }
        g_wsum[c] = aw; g_wbeta[c] = ab;
    }
}

// ================= Kernel 1: QKV GEMM (async, LN in epilogue, N-split) =======
// Block: M=64 x N=96 (2 N-halves), K chunks of 64, double-buffered cp.async.
// 8 warps: wm=warp>>1 (4), wn=warp&1 (2); warp tile 16x48.
#define K1_KC 64
#define ASTR 68
#define BSTR 68
#define K1_SMEM ((2*64*ASTR + 2*96*BSTR) * sizeof(float))

__global__ void __launch_bounds__(256, 2)
qkv_gemm_kernel(const float* __restrict__ x)
{
    extern __shared__ float sm1[];
    float* A_s = sm1;                    // [2][64][68]  raw x
    float* B_s = sm1 + 2 * 64 * ASTR;    // [2][96][68]  tf32 W'

    const int tid  = threadIdx.x;
    const int warp = tid >> 5;
    const int lane = tid & 31;
    const int rowBase = (blockIdx.x >> 1) * 64;
    const int nbase   = (blockIdx.x & 1) * 96;

    const uint32_t a_u = smem_u32(A_s);
    const uint32_t b_u = smem_u32(B_s);

    const int wm  = warp >> 1;   // 0..3
    const int wn  = warp & 1;    // 0..1
    const int grp = lane >> 2;
    const int tig = lane & 3;

    // stage chunk 0
    {
        #pragma unroll
        for (int i = 0; i < 4; i++) {
            const int idx = tid + 256 * i;
            const int row = idx >> 4, c4 = idx & 15;
            CP_ASYNC16(a_u + (row * ASTR + c4 * 4) * 4,
                       x + (size_t)(rowBase + row) * EMB + c4 * 4);
        }
        #pragma unroll
        for (int i = 0; i < 6; i++) {
            const int idx = tid + 256 * i;
            const int c = idx >> 4, c4 = idx & 15;
            CP_ASYNC16(b_u + (c * BSTR + c4 * 4) * 4,
                       g_w + (size_t)(nbase + c) * EMB + c4 * 4);
        }
        CP_COMMIT();
    }

    float acc[6][4];
    #pragma unroll
    for (int i = 0; i < 6; i++)
        #pragma unroll
        for (int j = 0; j < 4; j++) acc[i][j] = 0.f;

    for (int ch = 0; ch < EMB / K1_KC; ch++) {
        const int buf = ch & 1;

        if (ch + 1 < EMB / K1_KC) {
            const int nb = (ch + 1) & 1;
            const int k0 = (ch + 1) * K1_KC;
            #pragma unroll
            for (int i = 0; i < 4; i++) {
                const int idx = tid + 256 * i;
                const int row = idx >> 4, c4 = idx & 15;
                CP_ASYNC16(a_u + (nb * 64 * ASTR + row * ASTR + c4 * 4) * 4,
                           x + (size_t)(rowBase + row) * EMB + k0 + c4 * 4);
            }
            #pragma unroll
            for (int i = 0; i < 6; i++) {
                const int idx = tid + 256 * i;
                const int c = idx >> 4, c4 = idx & 15;
                CP_ASYNC16(b_u + (nb * 96 * BSTR + c * BSTR + c4 * 4) * 4,
                           g_w + (size_t)(nbase + c) * EMB + k0 + c4 * 4);
            }
            CP_COMMIT();
            CP_WAIT(1);
        } else {
            CP_WAIT(0);
        }
        __syncthreads();

        const float* Ab = A_s + buf * 64 * ASTR;
        const float* Bb = B_s + buf * 96 * BSTR;

        #pragma unroll
        for (int k8 = 0; k8 < 8; k8++) {
            const int kk = k8 * 8;
            uint32_t a[4];
            const int rr = wm * 16 + grp;
            a[0] = f2tf32(Ab[rr * ASTR + kk + tig]);
            a[1] = f2tf32(Ab[(rr + 8) * ASTR + kk + tig]);
            a[2] = f2tf32(Ab[rr * ASTR + kk + tig + 4]);
            a[3] = f2tf32(Ab[(rr + 8) * ASTR + kk + tig + 4]);
            #pragma unroll
            for (int tn = 0; tn < 6; tn++) {
                const int bc = wn * 48 + tn * 8 + grp;
                const uint32_t b0 = __float_as_uint(Bb[bc * BSTR + kk + tig]);
                const uint32_t b1 = __float_as_uint(Bb[bc * BSTR + kk + tig + 4]);
                mma_tf32(acc[tn], a, b0, b1);
            }
        }
        __syncthreads();
    }

    // epilogue: out = rs*(acc - mu*wsum) + wbeta, tf32-round, scatter
    {
        const int r0 = rowBase + wm * 16 + grp;
        const float mu0 = g_mu[r0],     rs0 = g_rs[r0];
        const float mu1 = g_mu[r0 + 8], rs1 = g_rs[r0 + 8];
        #pragma unroll
        for (int tn = 0; tn < 6; tn++) {
            const int c = nbase + wn * 48 + tn * 8 + tig * 2;
            const float ws0 = g_wsum[c],   wb0 = g_wbeta[c];
            const float ws1 = g_wsum[c+1], wb1 = g_wbeta[c+1];
            float* dst = (c < 64)  ? (g_q + (size_t)r0 * HEAD + c)
                       : (c < 128) ? (g_k + (size_t)r0 * HEAD + (c - 64))
                                   : (g_v + (size_t)r0 * HEAD + (c - 128));
            *(float2*)dst = make_float2(
                tf32r(rs0 * (acc[tn][0] - mu0 * ws0) + wb0),
                tf32r(rs0 * (acc[tn][1] - mu0 * ws1) + wb1));
            *(float2*)(dst + 8 * HEAD) = make_float2(
                tf32r(rs1 * (acc[tn][2] - mu1 * ws0) + wb0),
                tf32r(rs1 * (acc[tn][3] - mu1 * ws1) + wb1));
        }
    }
}

// ================= Kernel 2: causal flash attention (tf32 mma, split-KV x4) ===
// Grid = 4 batches x 32 q-tiles x 4 quarters = 512 blocks, 128 threads.
// Quarter h processes KV tiles {h, h+4, ...} <= qt. Q loaded via LDG (no smem).
#define KSTR 68
#define VSTR 72
#define K2_SMEM ((2*64*KSTR + 2*64*VSTR) * sizeof(float))

__global__ void __launch_bounds__(128, 3)
attn_mma_kernel()
{
    extern __shared__ float sm2[];
    float* k_s = sm2;                   // [2][64][68]
    float* v_s = k_s + 2 * 64 * KSTR;   // [2][64][72]

    const int tid  = threadIdx.x;
    const int warp = tid >> 5;
    const int lane = tid & 31;
    const int grp  = lane >> 2;
    const int tig  = lane & 3;

    const int b  = blockIdx.x >> 7;
    const int qt = 31 - ((blockIdx.x >> 2) & 31);   // heavy tiles launch first
    const int h  = blockIdx.x & 3;
    const int qbase = qt * 64;
    const int nkv = (qt >= h) ? (((qt - h) >> 2) + 1) : 0;

    float* OM = g_om + ((size_t)h * NROWS + (size_t)b * SEQ + qbase) * HEAD;
    float* M_ = g_m + (size_t)h * NROWS + (size_t)b * SEQ + qbase;
    float* L_ = g_l + (size_t)h * NROWS + (size_t)b * SEQ + qbase;

    const int rl0 = warp * 16 + grp;
    const int rl1 = rl0 + 8;

    if (nkv == 0) {  // empty quarter: neutral partials
        float4* om4 = (float4*)OM;
        for (int i = tid; i < 64 * 16; i += 128)
            om4[i] = make_float4(0.f, 0.f, 0.f, 0.f);
        if (tid < 64) { M_[tid] = -1e30f; L_[tid] = 0.f; }
        return;
    }

    const float* K = g_k + (size_t)b * SEQ * HEAD;
    const float* V = g_v + (size_t)b * SEQ * HEAD;

    const uint32_t k_u = smem_u32(k_s);
    const uint32_t v_u = smem_u32(v_s);

    // prefetch first KV tile (index h)
    {
        const float* Kg = K + (size_t)h * 64 * HEAD;
        const float* Vg = V + (size_t)h * 64 * HEAD;
        #pragma unroll
        for (int i = 0; i < 8; i++) {
            const int idx = tid + 128 * i;
            const int row = idx >> 4, c4 = idx & 15;
            CP_ASYNC16(k_u + (row * KSTR + c4 * 4) * 4, Kg + row * HEAD + c4 * 4);
            CP_ASYNC16(v_u + (row * VSTR + c4 * 4) * 4, Vg + row * HEAD + c4 * 4);
        }
        CP_COMMIT();
    }

    // Q fragments straight from gmem (L2-resident, overlaps cp.async).
    // Values already tf32; *0.125f (2^-3) is exact.
    uint32_t qa[8][4];
    {
        const float* Qr0 = g_q + ((size_t)b * SEQ + qbase + rl0) * HEAD;
        const float* Qr1 = g_q + ((size_t)b * SEQ + qbase + rl1) * HEAD;
        #pragma unroll
        for (int kc = 0; kc < 8; kc++) {
            const int kk = kc * 8;
            qa[kc][0] = __float_as_uint(0.125f * __ldg(Qr0 + kk + tig));
            qa[kc][1] = __float_as_uint(0.125f * __ldg(Qr1 + kk + tig));
            qa[kc][2] = __float_as_uint(0.125f * __ldg(Qr0 + kk + tig + 4));
            qa[kc][3] = __float_as_uint(0.125f * __ldg(Qr1 + kk + tig + 4));
        }
    }

    float o[8][4];
    #pragma unroll
    for (int nt = 0; nt < 8; nt++)
        #pragma unroll
        for (int j = 0; j < 4; j++) o[nt][j] = 0.f;
    float m0 = -1e30f, m1 = -1e30f, l0 = 0.f, l1 = 0.f;

    const int src_lo = (grp << 2) + (tig >> 1);
    const int src_hi = src_lo + 2;

    for (int i = 0; i < nkv; i++) {
        const int kt  = h + 4 * i;
        const int buf = i & 1;

        if (i + 1 < nkv) {
            const int nb = (i + 1) & 1;
            const float* Kg = K + (size_t)(kt + 4) * 64 * HEAD;
            const float* Vg = V + (size_t)(kt + 4) * 64 * HEAD;
            #pragma unroll
            for (int u = 0; u < 8; u++) {
                const int idx = tid + 128 * u;
                const int row = idx >> 4, c4 = idx & 15;
                CP_ASYNC16(k_u + (nb * 64 * KSTR + row * KSTR + c4 * 4) * 4,
                           Kg + row * HEAD + c4 * 4);
                CP_ASYNC16(v_u + (nb * 64 * VSTR + row * VSTR + c4 * 4) * 4,
                           Vg + row * HEAD + c4 * 4);
            }
            CP_COMMIT();
            CP_WAIT(1);
        } else {
            CP_WAIT(0);
        }
        __syncthreads();

        const float* kb_s = k_s + buf * 64 * KSTR;
        const float* vb_s = v_s + buf * 64 * VSTR;

        // S = Q K^T
        float s[8][4];
        #pragma unroll
        for (int nt = 0; nt < 8; nt++)
            #pragma unroll
            for (int j = 0; j < 4; j++) s[nt][j] = 0.f;

        #pragma unroll
        for (int kc = 0; kc < 8; kc++) {
            const int kk = kc * 8;
            #pragma unroll
            for (int nt = 0; nt < 8; nt++) {
                const int n = nt * 8 + grp;
                const uint32_t b0 = __float_as_uint(kb_s[n * KSTR + kk + tig]);
                const uint32_t b1 = __float_as_uint(kb_s[n * KSTR + kk + tig + 4]);
                mma_tf32(s[nt], qa[kc], b0, b1);
            }
        }

        if (kt == qt) {
            #pragma unroll
            for (int nt = 0; nt < 8; nt++) {
                const int c0 = nt * 8 + 2 * tig;
                if (c0     > rl0) s[nt][0] = -1e30f;
                if (c0 + 1 > rl0) s[nt][1] = -1e30f;
                if (c0     > rl1) s[nt][2] = -1e30f;
                if (c0 + 1 > rl1) s[nt][3] = -1e30f;
            }
        }

        // online softmax (register/quad only)
        float mx0 = -1e30f, mx1 = -1e30f;
        #pragma unroll
        for (int nt = 0; nt < 8; nt++) {
            mx0 = fmaxf(mx0, fmaxf(s[nt][0], s[nt][1]));
            mx1 = fmaxf(mx1, fmaxf(s[nt][2], s[nt][3]));
        }
        mx0 = fmaxf(mx0, __shfl_xor_sync(0xffffffffu, mx0, 1));
        mx0 = fmaxf(mx0, __shfl_xor_sync(0xffffffffu, mx0, 2));
        mx1 = fmaxf(mx1, __shfl_xor_sync(0xffffffffu, mx1, 1));
        mx1 = fmaxf(mx1, __shfl_xor_sync(0xffffffffu, mx1, 2));

        const float mn0 = fmaxf(m0, mx0);
        const float mn1 = fmaxf(m1, mx1);
        const float cor0 = __expf(m0 - mn0);
        const float cor1 = __expf(m1 - mn1);
        m0 = mn0; m1 = mn1;

        float sum0 = 0.f, sum1 = 0.f;
        #pragma unroll
        for (int nt = 0; nt < 8; nt++) {
            s[nt][0] = __expf(s[nt][0] - mn0);
            s[nt][1] = __expf(s[nt][1] - mn0);
            s[nt][2] = __expf(s[nt][2] - mn1);
            s[nt][3] = __expf(s[nt][3] - mn1);
            sum0 += s[nt][0] + s[nt][1];
            sum1 += s[nt][2] + s[nt][3];
        }
        sum0 += __shfl_xor_sync(0xffffffffu, sum0, 1);
        sum0 += __shfl_xor_sync(0xffffffffu, sum0, 2);
        sum1 += __shfl_xor_sync(0xffffffffu, sum1, 1);
        sum1 += __shfl_xor_sync(0xffffffffu, sum1, 2);
        l0 = l0 * cor0 + sum0;
        l1 = l1 * cor1 + sum1;

        #pragma unroll
        for (int nt = 0; nt < 8; nt++) {
            o[nt][0] *= cor0; o[nt][1] *= cor0;
            o[nt][2] *= cor1; o[nt][3] *= cor1;
        }

        // P (C-frag) -> A-frag via quad shuffles
        uint32_t pa[8][4];
        #pragma unroll
        for (int kc = 0; kc < 8; kc++) {
            const float v0 = __shfl_sync(0xffffffffu, s[kc][0], src_lo);
            const float v1 = __shfl_sync(0xffffffffu, s[kc][1], src_lo);
            const float v2 = __shfl_sync(0xffffffffu, s[kc][2], src_lo);
            const float v3 = __shfl_sync(0xffffffffu, s[kc][3], src_lo);
            const float w0 = __shfl_sync(0xffffffffu, s[kc][0], src_hi);
            const float w1 = __shfl_sync(0xffffffffu, s[kc][1], src_hi);
            const float w2 = __shfl_sync(0xffffffffu, s[kc][2], src_hi);
            const float w3 = __shfl_sync(0xffffffffu, s[kc][3], src_hi);
            pa[kc][0] = f2tf32((tig & 1) ? v1 : v0);
            pa[kc][1] = f2tf32((tig & 1) ? v3 : v2);
            pa[kc][2] = f2tf32((tig & 1) ? w1 : w0);
            pa[kc][3] = f2tf32((tig & 1) ? w3 : w2);
        }

        // O += P V
        #pragma unroll
        for (int kc = 0; kc < 8; kc++) {
            const int k0 = kc * 8;
            #pragma unroll
            for (int nt = 0; nt < 8; nt++) {
                const int n = nt * 8 + grp;
                const uint32_t b0 = __float_as_uint(vb_s[(k0 + tig) * VSTR + n]);
                const uint32_t b1 = __float_as_uint(vb_s[(k0 + tig + 4) * VSTR + n]);
                mma_tf32(o[nt], pa[kc], b0, b1);
            }
        }

        __syncthreads();
    }

    // epilogue: unnormalized partials + stats
    #pragma unroll
    for (int nt = 0; nt < 8; nt++) {
        const int c = nt * 8 + 2 * tig;
        *(float2*)(OM + (size_t)rl0 * HEAD + c) = make_float2(o[nt][0], o[nt][1]);
        *(float2*)(OM + (size_t)rl1 * HEAD + c) = make_float2(o[nt][2], o[nt][3]);
    }
    if (tig == 0) {
        M_[rl0] = m0; L_[rl0] = l0;
        M_[rl1] = m1; L_[rl1] = l1;
    }
}

// ================= Kernel 3: split-KV combine (4 partials) =================
__global__ void __launch_bounds__(256)
combine_kernel(float* __restrict__ out)
{
    const int idx = blockIdx.x * 256 + threadIdx.x;
    const int row = idx >> 4;
    const int c4  = idx & 15;

    float m[SPLITK], l[SPLITK];
    float M = -1e30f;
    #pragma unroll
    for (int h = 0; h < SPLITK; h++) {
        m[h] = g_m[h * NROWS + row];
        l[h] = g_l[h * NROWS + row];
        M = fmaxf(M, m[h]);
    }
    float denom = 0.f, a[SPLITK];
    #pragma unroll
    for (int h = 0; h < SPLITK; h++) {
        a[h] = __expf(m[h] - M);
        denom += l[h] * a[h];
    }
    const float inv = 1.0f / denom;

    float4 r = make_float4(0.f, 0.f, 0.f, 0.f);
    #pragma unroll
    for (int h = 0; h < SPLITK; h++) {
        const float w = a[h] * inv;
        const float4 oh = *(const float4*)(g_om + ((size_t)h * NROWS + row) * HEAD + c4 * 4);
        r.x += oh.x * w; r.y += oh.y * w;
        r.z += oh.z * w; r.w += oh.w * w;
    }
    *(float4*)(out + (size_t)row * HEAD + c4 * 4) = r;
}

// ================= launch =================
extern "C" void kernel_launch(void* const* d_in, const int* in_sizes, int n_in,
                              void* d_out, int out_size)
{
    const float* x     = (const float*)d_in[0];
    const float* gamma = (const float*)d_in[1];
    const float* beta  = (const float*)d_in[2];
    const float* Wq    = (const float*)d_in[3];
    const float* Wk    = (const float*)d_in[4];
    const float* Wv    = (const float*)d_in[5];
    float* out = (float*)d_out;

    cudaFuncSetAttribute(qkv_gemm_kernel, cudaFuncAttributeMaxDynamicSharedMemorySize, (int)K1_SMEM);
    cudaFuncSetAttribute(attn_mma_kernel, cudaFuncAttributeMaxDynamicSharedMemorySize, (int)K2_SMEM);

    ln_stats_kernel<<<NROWS / 8, 256>>>(x);
    wprep_kernel<<<192, 256>>>(gamma, beta, Wq, Wk, Wv);
    qkv_gemm_kernel<<<(NROWS / 64) * 2, 256, K1_SMEM>>>(x);
    attn_mma_kernel<<<BATCH * 32 * SPLITK, 128, K2_SMEM>>>();
    combine_kernel<<<NROWS * 16 / 256, 256>>>(out);
}